// round 7
// baseline (speedup 1.0000x reference)
#include <cuda_runtime.h>
#include <cuda_fp16.h>
#include <cstdint>

#define NN 4096
#define FIN 512
#define FO 64
#define NH 8
#define ALPHA 0.2f
#define OUTW (NH * FO)  /* 512 */
#define LOG2E 1.4426950408889634f
#define NWORD (NN / 32)  /* 128 */

// ---------------------------------------------------------------------------
// Scratch (static device globals)
// ---------------------------------------------------------------------------
__device__ unsigned short g_h16hi[NN * FIN];     // fp16 hi of h, [n][k]
__device__ unsigned short g_h16lo[NN * FIN];     // fp16 lo of h, [n][k]
__device__ unsigned short g_w16hi[NH * FIN * FO];// fp16 hi of W, [h][k][n]
__device__ unsigned short g_w16lo[NH * FIN * FO];
__device__ unsigned short g_wh16[NH * NN * FO];  // fp16 Wh, [h][n][o]
__device__ float g_el[NH * NN];                  // el * log2e (incl bA)
__device__ float g_er[NH * NN];                  // er * log2e
__device__ unsigned int g_ermax_enc[NH];         // order-preserving encoded max
__device__ uint32_t g_bits[NN * NWORD];          // mask bitmap [i][j/32]

__device__ __forceinline__ uint32_t smem_u32(const void* p) {
    uint32_t a;
    asm("{ .reg .u64 t; cvta.to.shared.u64 t, %1; cvt.u32.u64 %0, t; }" : "=r"(a) : "l"(p));
    return a;
}

// order-preserving float <-> uint encoding (for atomicMax on any-sign floats)
__device__ __forceinline__ unsigned int f2ord(float f) {
    unsigned int u = __float_as_uint(f);
    return (u & 0x80000000u) ? ~u : (u | 0x80000000u);
}
__device__ __forceinline__ float ord2f(unsigned int k) {
    unsigned int u = (k & 0x80000000u) ? (k & 0x7FFFFFFFu) : ~k;
    return __uint_as_float(u);
}

#define MMA16816F16(acc, a0, a1, a2, a3, b0, b1) \
    asm volatile("mma.sync.aligned.m16n8k16.row.col.f32.f16.f16.f32 " \
        "{%0,%1,%2,%3}, {%4,%5,%6,%7}, {%8,%9}, {%0,%1,%2,%3};" \
        : "+f"((acc)[0]), "+f"((acc)[1]), "+f"((acc)[2]), "+f"((acc)[3]) \
        : "r"(a0), "r"(a1), "r"(a2), "r"(a3), "r"(b0), "r"(b1))

#define LDSM4T(r0, r1, r2, r3, a) \
    asm volatile("ldmatrix.sync.aligned.m8n8.x4.trans.shared.b16 {%0,%1,%2,%3}, [%4];" \
        : "=r"(r0), "=r"(r1), "=r"(r2), "=r"(r3) : "r"(a))

#define LDSM4(r0, r1, r2, r3, a) \
    asm volatile("ldmatrix.sync.aligned.m8n8.x4.shared.b16 {%0,%1,%2,%3}, [%4];" \
        : "=r"(r0), "=r"(r1), "=r"(r2), "=r"(r3) : "r"(a))

__device__ __forceinline__ uint32_t pack_hi_f16x2(float a, float b) {
    uint32_t r;
    asm("cvt.rn.f16x2.f32 %0, %1, %2;" : "=r"(r) : "f"(b), "f"(a));
    return r;
}

// ---------------------------------------------------------------------------
// Kernel P: convert h and W to fp16 hi/lo; init ermax accumulators.
// ---------------------------------------------------------------------------
__global__ void __launch_bounds__(256) prep_kernel(
    const float* __restrict__ h, const float* __restrict__ W)
{
    if (blockIdx.x == 0 && threadIdx.x < NH)
        g_ermax_enc[threadIdx.x] = 0u;  // below every encoded float

    const int stride = gridDim.x * 256;
    for (int i = blockIdx.x * 256 + threadIdx.x; i < NN * FIN / 4; i += stride) {
        float4 v = ((const float4*)h)[i];
        __half hx = __float2half_rn(v.x), hy = __float2half_rn(v.y);
        __half hz = __float2half_rn(v.z), hw = __float2half_rn(v.w);
        uint32_t hi0 = (uint32_t)__half_as_ushort(hx) | ((uint32_t)__half_as_ushort(hy) << 16);
        uint32_t hi1 = (uint32_t)__half_as_ushort(hz) | ((uint32_t)__half_as_ushort(hw) << 16);
        uint32_t lo0 = pack_hi_f16x2(v.x - __half2float(hx), v.y - __half2float(hy));
        uint32_t lo1 = pack_hi_f16x2(v.z - __half2float(hz), v.w - __half2float(hw));
        ((uint2*)g_h16hi)[i] = make_uint2(hi0, hi1);
        ((uint2*)g_h16lo)[i] = make_uint2(lo0, lo1);
    }
    for (int i = blockIdx.x * 256 + threadIdx.x; i < NH * FIN * FO / 4; i += stride) {
        float4 v = ((const float4*)W)[i];
        __half hx = __float2half_rn(v.x), hy = __float2half_rn(v.y);
        __half hz = __float2half_rn(v.z), hw = __float2half_rn(v.w);
        uint32_t hi0 = (uint32_t)__half_as_ushort(hx) | ((uint32_t)__half_as_ushort(hy) << 16);
        uint32_t hi1 = (uint32_t)__half_as_ushort(hz) | ((uint32_t)__half_as_ushort(hw) << 16);
        uint32_t lo0 = pack_hi_f16x2(v.x - __half2float(hx), v.y - __half2float(hy));
        uint32_t lo1 = pack_hi_f16x2(v.z - __half2float(hz), v.w - __half2float(hw));
        ((uint2*)g_w16hi)[i] = make_uint2(hi0, hi1);
        ((uint2*)g_w16lo)[i] = make_uint2(lo0, lo1);
    }
}

// ---------------------------------------------------------------------------
// Kernel A: Wh = h @ W + bW via fp16 HMMA hi/lo split; fused el/er and
// per-head er-max (CTA reduce + 1 atomicMax).
// ---------------------------------------------------------------------------
#define ASTRIDE 72
#define WH_SMEM (128 * ASTRIDE * 2 * 2 + 64 * ASTRIDE * 2 * 2)

__global__ void __launch_bounds__(256) wh_mma_kernel(
    const float* __restrict__ bW, const float* __restrict__ a_l,
    const float* __restrict__ a_r, const float* __restrict__ bA)
{
    extern __shared__ __align__(16) unsigned short sm[];
    unsigned short* Ah = sm;
    unsigned short* Al = Ah + 128 * ASTRIDE;
    unsigned short* Bh = Al + 128 * ASTRIDE;
    unsigned short* Bl = Bh + 64 * ASTRIDE;
    __shared__ float redmax[8];

    const int t    = threadIdx.x;
    const int warp = t >> 5;
    const int lane = t & 31;
    const int i0   = blockIdx.x * 128;
    const int hh   = blockIdx.y;

    const uint32_t ahB = smem_u32(Ah), alB = smem_u32(Al);
    const uint32_t bhB = smem_u32(Bh), blB = smem_u32(Bl);

    float acc[8][4];
#pragma unroll
    for (int n = 0; n < 8; n++)
#pragma unroll
        for (int j = 0; j < 4; j++) acc[n][j] = 0.f;

    const uint32_t aRow = (uint32_t)(16 * warp + (lane & 15)) * (ASTRIDE * 2) + ((lane & 16) ? 16 : 0);
    const uint32_t bRow = (uint32_t)(lane & 15) * (ASTRIDE * 2) + ((lane & 16) ? 16 : 0);

    for (int ch = 0; ch < FIN / 64; ch++) {
        const int kc = ch * 64;
        __syncthreads();
#pragma unroll
        for (int it = 0; it < 4; it++) {
            int id = t + 256 * it;
            int r = id >> 3, c = id & 7;
            size_t src = (size_t)(i0 + r) * FIN + kc + c * 8;
            *(uint4*)&Ah[r * ASTRIDE + c * 8] = *(const uint4*)(g_h16hi + src);
            *(uint4*)&Al[r * ASTRIDE + c * 8] = *(const uint4*)(g_h16lo + src);
        }
#pragma unroll
        for (int it = 0; it < 2; it++) {
            int id = t + 256 * it;
            int r = id >> 3, c = id & 7;
            size_t src = ((size_t)hh * FIN + kc + r) * FO + c * 8;
            *(uint4*)&Bh[r * ASTRIDE + c * 8] = *(const uint4*)(g_w16hi + src);
            *(uint4*)&Bl[r * ASTRIDE + c * 8] = *(const uint4*)(g_w16lo + src);
        }
        __syncthreads();

#pragma unroll
        for (int kt = 0; kt < 4; kt++) {
            uint32_t ah0, ah1, ah2, ah3, al0, al1, al2, al3;
            LDSM4(ah0, ah1, ah2, ah3, ahB + aRow + kt * 32);
            LDSM4(al0, al1, al2, al3, alB + aRow + kt * 32);
            const uint32_t kOff = (uint32_t)(16 * kt) * (ASTRIDE * 2) + bRow;
#pragma unroll
            for (int ntp = 0; ntp < 4; ntp++) {
                uint32_t bh0, bh1, bh2, bh3, bl0, bl1, bl2, bl3;
                LDSM4T(bh0, bh1, bh2, bh3, bhB + kOff + 32 * ntp);
                LDSM4T(bl0, bl1, bl2, bl3, blB + kOff + 32 * ntp);
                MMA16816F16(acc[2 * ntp],     ah0, ah1, ah2, ah3, bh0, bh1);
                MMA16816F16(acc[2 * ntp],     al0, al1, al2, al3, bh0, bh1);
                MMA16816F16(acc[2 * ntp],     ah0, ah1, ah2, ah3, bl0, bl1);
                MMA16816F16(acc[2 * ntp + 1], ah0, ah1, ah2, ah3, bh2, bh3);
                MMA16816F16(acc[2 * ntp + 1], al0, al1, al2, al3, bh2, bh3);
                MMA16816F16(acc[2 * ntp + 1], ah0, ah1, ah2, ah3, bl2, bl3);
            }
        }
    }

    // ---- epilogue: bias, store fp16 Wh, fused el/er, er-max ----
    const int q  = lane >> 2;
    const int c2 = 2 * (lane & 3);
    const int r0 = i0 + 16 * warp + q;
    const int r1 = r0 + 8;

    float dl0 = 0.f, dr0 = 0.f, dl1 = 0.f, dr1 = 0.f;
#pragma unroll
    for (int nt = 0; nt < 8; nt++) {
        int col = 8 * nt + c2;
        float2 bw = *(const float2*)(bW + hh * FO + col);
        float2 al = *(const float2*)(a_l + hh * FO + col);
        float2 ar = *(const float2*)(a_r + hh * FO + col);
        float v00 = acc[nt][0] + bw.x, v01 = acc[nt][1] + bw.y;
        float v10 = acc[nt][2] + bw.x, v11 = acc[nt][3] + bw.y;
        *(uint32_t*)(g_wh16 + ((size_t)hh * NN + r0) * FO + col) = pack_hi_f16x2(v00, v01);
        *(uint32_t*)(g_wh16 + ((size_t)hh * NN + r1) * FO + col) = pack_hi_f16x2(v10, v11);
        dl0 += v00 * al.x + v01 * al.y;
        dr0 += v00 * ar.x + v01 * ar.y;
        dl1 += v10 * al.x + v11 * al.y;
        dr1 += v10 * ar.x + v11 * ar.y;
    }
#pragma unroll
    for (int off = 1; off < 4; off <<= 1) {
        dl0 += __shfl_xor_sync(0xffffffffu, dl0, off);
        dr0 += __shfl_xor_sync(0xffffffffu, dr0, off);
        dl1 += __shfl_xor_sync(0xffffffffu, dl1, off);
        dr1 += __shfl_xor_sync(0xffffffffu, dr1, off);
    }
    float er0s = dr0 * LOG2E, er1s = dr1 * LOG2E;
    if ((lane & 3) == 0) {
        float ba = bA[hh];
        g_el[hh * NN + r0] = (dl0 + ba) * LOG2E;
        g_er[hh * NN + r0] = er0s;
        g_el[hh * NN + r1] = (dl1 + ba) * LOG2E;
        g_er[hh * NN + r1] = er1s;
    }
    // warp max of er over its 16 rows -> smem -> one atomic per CTA
    float wm = fmaxf(er0s, er1s);
#pragma unroll
    for (int off = 4; off < 32; off <<= 1)
        wm = fmaxf(wm, __shfl_xor_sync(0xffffffffu, wm, off));
    if (lane == 0) redmax[warp] = wm;
    __syncthreads();
    if (t == 0) {
        float m = redmax[0];
#pragma unroll
        for (int w = 1; w < 8; w++) m = fmaxf(m, redmax[w]);
        atomicMax(&g_ermax_enc[hh], f2ord(m));
    }
}

// ---------------------------------------------------------------------------
// Kernel A2: mask -> bitmap
// ---------------------------------------------------------------------------
__global__ void __launch_bounds__(256) mask_bits_kernel(const int* __restrict__ mask)
{
    int gw   = (blockIdx.x * 256 + threadIdx.x) >> 5;
    int lane = threadIdx.x & 31;
    int row  = gw >> 7;
    int wd   = gw & (NWORD - 1);
    int m = mask[(size_t)row * NN + wd * 32 + lane];
    uint32_t b = __ballot_sync(0xffffffffu, m > 0);
    if (lane == 0) g_bits[gw] = b;
}

// ---------------------------------------------------------------------------
// Kernel C: fp16 HMMA flash-GAT, f16x2 fused score math.
// Per pair of j: x = el'+er (f32 adds), pack->f16x2, y = fma.f16x2(alpha,x,d2),
// p = ex2(max(x,y)) & mask. d2 = dup-f16((ALPHA-1)*c); per-row constant fp16
// rounding of el' cancels in the softmax ratio.
// ---------------------------------------------------------------------------
__device__ __forceinline__ float elu(float v) {
    return v > 0.f ? v : (__expf(v) - 1.f);
}

#define ALPHA2_F16 0x32663266u  /* (0.2, 0.2) fp16x2 */

__device__ __forceinline__ uint32_t pscore2(float elp, uint32_t d2, float2 er, uint32_t b2) {
    float x0 = elp + er.x;
    float x1 = elp + er.y;
    uint32_t xh, yh, mh, pe;
    asm("cvt.rn.f16x2.f32 %0, %1, %2;" : "=r"(xh) : "f"(x1), "f"(x0));
    asm("fma.rn.f16x2 %0, %1, %2, %3;" : "=r"(yh) : "r"(ALPHA2_F16), "r"(xh), "r"(d2));
    asm("max.f16x2 %0, %1, %2;" : "=r"(mh) : "r"(xh), "r"(yh));
    asm("ex2.approx.f16x2 %0, %1;" : "=r"(pe) : "r"(mh));
    uint32_t msk = ((b2 & 1u) ? 0x0000FFFFu : 0u) | ((b2 & 2u) ? 0xFFFF0000u : 0u);
    return pe & msk;
}

#define BSTRIDE 72

__global__ void __launch_bounds__(256, 2) gat_attn_mma_kernel(float* __restrict__ out)
{
    __shared__ __align__(16) unsigned short Bs[2][64 * BSTRIDE];
    __shared__ float2 els2[128];   // {el - c, bitcast(dup-f16((ALPHA-1)c))}

    const int t    = threadIdx.x;
    const int warp = t >> 5;
    const int lane = t & 31;
    const int i0   = blockIdx.x * 128;
    const int hh   = blockIdx.y;

    if (t < 128) {
        float e = g_el[hh * NN + i0 + t];
        float z = e + ord2f(g_ermax_enc[hh]);
        float c = fmaxf(z, ALPHA * z);
        float d = (ALPHA - 1.f) * c;
        __half hd = __float2half_rn(d);
        uint32_t d2 = (uint32_t)__half_as_ushort(hd);
        d2 |= d2 << 16;
        els2[t] = make_float2(e - c, __uint_as_float(d2));
    }

    const int q  = lane >> 2;
    const int c2 = 2 * (lane & 3);
    const int rw0 = 16 * warp + q;

    const float* erb = g_er + hh * NN + c2;
    const unsigned short* gwh = g_wh16 + (size_t)hh * NN * FO;
    const uint32_t* bitrow = g_bits + (size_t)(i0 + 16 * warp + (lane >> 1)) * NWORD + (lane & 1);

    const uint32_t bBase = smem_u32(Bs);
    const uint32_t lrowOff = (uint32_t)(lane & 15) * (BSTRIDE * 2) + ((lane & 16) ? 16 : 0);

    const int lk0 = t >> 3, lc0 = t & 7;
    const int lk1 = (t + 256) >> 3, lc1 = t & 7;

    float acc[8][4];
#pragma unroll
    for (int n = 0; n < 8; n++)
#pragma unroll
        for (int j = 0; j < 4; j++) acc[n][j] = 0.f;
    float accd[4] = {0.f, 0.f, 0.f, 0.f};
    const uint32_t ONES = 0x3C003C00u;

    {
        uint4 va = *(const uint4*)(gwh + (size_t)lk0 * FO + lc0 * 8);
        uint4 vb = *(const uint4*)(gwh + (size_t)lk1 * FO + lc1 * 8);
        *(uint4*)&Bs[0][lk0 * BSTRIDE + lc0 * 8] = va;
        *(uint4*)&Bs[0][lk1 * BSTRIDE + lc1 * 8] = vb;
    }
    __syncthreads();

    const float2 ec0 = els2[rw0];
    const float2 ec1 = els2[rw0 + 8];
    const float elp0 = ec0.x, elp1 = ec1.x;
    const uint32_t d20 = __float_as_uint(ec0.y), d21 = __float_as_uint(ec1.y);

    for (int tile = 0; tile < NN / 64; tile++) {
        const int j0 = tile * 64;
        const int cur = tile & 1;

        uint32_t bv = bitrow[(uint32_t)(j0 >> 5)];
        uint32_t w00 = __shfl_sync(0xffffffffu, bv, 2 * q);
        uint32_t w01 = __shfl_sync(0xffffffffu, bv, 2 * q + 1);
        uint32_t w10 = __shfl_sync(0xffffffffu, bv, 2 * q + 16);
        uint32_t w11 = __shfl_sync(0xffffffffu, bv, 2 * q + 17);

        uint4 na, nb;
        if (tile < NN / 64 - 1) {
            const unsigned short* src = gwh + (size_t)(j0 + 64) * FO;
            na = *(const uint4*)(src + (size_t)lk0 * FO + lc0 * 8);
            nb = *(const uint4*)(src + (size_t)lk1 * FO + lc1 * 8);
        }

        const uint32_t bufOff = bBase + cur * (64 * BSTRIDE * 2) + lrowOff;

#pragma unroll
        for (int kt = 0; kt < 4; kt++) {
            const int jb = j0 + 16 * kt;
            float2 e0 = *(const float2*)(erb + jb);
            float2 e1 = *(const float2*)(erb + jb + 8);

            uint32_t wr0 = (kt < 2) ? w00 : w01;
            uint32_t wr1 = (kt < 2) ? w10 : w11;
            const int sb = (kt & 1) * 16;
            uint32_t v0 = wr0 >> (sb + c2);
            uint32_t v1 = wr1 >> (sb + c2);

            uint32_t a0 = pscore2(elp0, d20, e0, v0 & 3u);
            uint32_t a1 = pscore2(elp1, d21, e0, v1 & 3u);
            uint32_t a2 = pscore2(elp0, d20, e1, (v0 >> 8) & 3u);
            uint32_t a3 = pscore2(elp1, d21, e1, (v1 >> 8) & 3u);

            const uint32_t kOff = bufOff + (uint32_t)(16 * kt) * (BSTRIDE * 2);
#pragma unroll
            for (int ntp = 0; ntp < 4; ntp++) {
                uint32_t b0, b1, b2, b3;
                LDSM4T(b0, b1, b2, b3, kOff + 32 * ntp);
                MMA16816F16(acc[2 * ntp],     a0, a1, a2, a3, b0, b1);
                MMA16816F16(acc[2 * ntp + 1], a0, a1, a2, a3, b2, b3);
            }
            MMA16816F16(accd, a0, a1, a2, a3, ONES, ONES);
        }

        if (tile < NN / 64 - 1) {
            unsigned short* dst = &Bs[cur ^ 1][0];
            *(uint4*)&dst[lk0 * BSTRIDE + lc0 * 8] = na;
            *(uint4*)&dst[lk1 * BSTRIDE + lc1 * 8] = nb;
        }
        __syncthreads();
    }

    const float inv0 = 1.f / accd[0];
    const float inv1 = 1.f / accd[2];

    float* ob0 = out + (size_t)(i0 + rw0) * OUTW + hh * FO + c2;
    float* ob1 = ob0 + (size_t)8 * OUTW;
#pragma unroll
    for (int nt = 0; nt < 8; nt++) {
        float2 v0 = make_float2(elu(acc[nt][0] * inv0), elu(acc[nt][1] * inv0));
        float2 v1 = make_float2(elu(acc[nt][2] * inv1), elu(acc[nt][3] * inv1));
        *(float2*)(ob0 + 8 * nt) = v0;
        *(float2*)(ob1 + 8 * nt) = v1;
    }
}

// ---------------------------------------------------------------------------
extern "C" void kernel_launch(void* const* d_in, const int* in_sizes, int n_in,
                              void* d_out, int out_size)
{
    const float* h    = (const float*)d_in[0];  // [N, FIN]
    const int*   mask = (const int*)  d_in[1];  // [N, N]
    const float* W    = (const float*)d_in[2];  // [H, FIN, FO]
    const float* bW   = (const float*)d_in[3];  // [H, FO]
    const float* a_l  = (const float*)d_in[4];  // [H, FO]
    const float* a_r  = (const float*)d_in[5];  // [H, FO]
    const float* bA   = (const float*)d_in[6];  // [H]
    float* out = (float*)d_out;                 // [N, H*FO]

    cudaFuncSetAttribute(wh_mma_kernel,
                         cudaFuncAttributeMaxDynamicSharedMemorySize, WH_SMEM);

    prep_kernel<<<1024, 256>>>(h, W);
    wh_mma_kernel<<<dim3(NN / 128, NH), 256, WH_SMEM>>>(bW, a_l, a_r, bA);
    mask_bits_kernel<<<NN * NWORD / 8, 256>>>(mask);
    gat_attn_mma_kernel<<<dim3(NN / 128, NH), 256>>>(out);
}

// round 8
// speedup vs baseline: 1.4391x; 1.4391x over previous
#include <cuda_runtime.h>
#include <cuda_fp16.h>
#include <cstdint>

#define NN 4096
#define FIN 512
#define FO 64
#define NH 8
#define ALPHA 0.2f
#define OUTW (NH * FO)  /* 512 */
#define LOG2E 1.4426950408889634f
#define NWORD (NN / 32)  /* 128 */

// ---------------------------------------------------------------------------
// Scratch (static device globals)
// ---------------------------------------------------------------------------
__device__ unsigned short g_h16hi[NN * FIN];     // fp16 hi of h, [n][k]
__device__ unsigned short g_h16lo[NN * FIN];     // fp16 lo of h, [n][k]
__device__ unsigned short g_w16hi[NH * FIN * FO];// fp16 hi of W, [h][k][n]
__device__ unsigned short g_w16lo[NH * FIN * FO];
__device__ unsigned short g_wh16[NH * NN * FO];  // fp16 Wh, [h][n][o]
__device__ float g_el[NH * NN];                  // el * log2e (incl bA)
__device__ float g_er[NH * NN];                  // er * log2e
__device__ unsigned int g_ermax_enc[NH];         // order-preserving encoded max
__device__ uint32_t g_bits[NN * NWORD];          // mask bitmap [i][j/32]

__device__ __forceinline__ uint32_t smem_u32(const void* p) {
    uint32_t a;
    asm("{ .reg .u64 t; cvta.to.shared.u64 t, %1; cvt.u32.u64 %0, t; }" : "=r"(a) : "l"(p));
    return a;
}

// order-preserving float <-> uint encoding (for atomicMax on any-sign floats)
__device__ __forceinline__ unsigned int f2ord(float f) {
    unsigned int u = __float_as_uint(f);
    return (u & 0x80000000u) ? ~u : (u | 0x80000000u);
}
__device__ __forceinline__ float ord2f(unsigned int k) {
    unsigned int u = (k & 0x80000000u) ? (k & 0x7FFFFFFFu) : ~k;
    return __uint_as_float(u);
}

#define MMA16816F16(acc, a0, a1, a2, a3, b0, b1) \
    asm volatile("mma.sync.aligned.m16n8k16.row.col.f32.f16.f16.f32 " \
        "{%0,%1,%2,%3}, {%4,%5,%6,%7}, {%8,%9}, {%0,%1,%2,%3};" \
        : "+f"((acc)[0]), "+f"((acc)[1]), "+f"((acc)[2]), "+f"((acc)[3]) \
        : "r"(a0), "r"(a1), "r"(a2), "r"(a3), "r"(b0), "r"(b1))

#define LDSM4T(r0, r1, r2, r3, a) \
    asm volatile("ldmatrix.sync.aligned.m8n8.x4.trans.shared.b16 {%0,%1,%2,%3}, [%4];" \
        : "=r"(r0), "=r"(r1), "=r"(r2), "=r"(r3) : "r"(a))

#define LDSM4(r0, r1, r2, r3, a) \
    asm volatile("ldmatrix.sync.aligned.m8n8.x4.shared.b16 {%0,%1,%2,%3}, [%4];" \
        : "=r"(r0), "=r"(r1), "=r"(r2), "=r"(r3) : "r"(a))

__device__ __forceinline__ uint32_t pack_hi_f16x2(float a, float b) {
    uint32_t r;
    asm("cvt.rn.f16x2.f32 %0, %1, %2;" : "=r"(r) : "f"(b), "f"(a));
    return r;
}

// ---------------------------------------------------------------------------
// Kernel P: convert h and W to fp16 hi/lo; init ermax accumulators.
// ---------------------------------------------------------------------------
__global__ void __launch_bounds__(256) prep_kernel(
    const float* __restrict__ h, const float* __restrict__ W)
{
    if (blockIdx.x == 0 && threadIdx.x < NH)
        g_ermax_enc[threadIdx.x] = 0u;  // below every encoded float

    const int stride = gridDim.x * 256;
    for (int i = blockIdx.x * 256 + threadIdx.x; i < NN * FIN / 4; i += stride) {
        float4 v = ((const float4*)h)[i];
        __half hx = __float2half_rn(v.x), hy = __float2half_rn(v.y);
        __half hz = __float2half_rn(v.z), hw = __float2half_rn(v.w);
        uint32_t hi0 = (uint32_t)__half_as_ushort(hx) | ((uint32_t)__half_as_ushort(hy) << 16);
        uint32_t hi1 = (uint32_t)__half_as_ushort(hz) | ((uint32_t)__half_as_ushort(hw) << 16);
        uint32_t lo0 = pack_hi_f16x2(v.x - __half2float(hx), v.y - __half2float(hy));
        uint32_t lo1 = pack_hi_f16x2(v.z - __half2float(hz), v.w - __half2float(hw));
        ((uint2*)g_h16hi)[i] = make_uint2(hi0, hi1);
        ((uint2*)g_h16lo)[i] = make_uint2(lo0, lo1);
    }
    for (int i = blockIdx.x * 256 + threadIdx.x; i < NH * FIN * FO / 4; i += stride) {
        float4 v = ((const float4*)W)[i];
        __half hx = __float2half_rn(v.x), hy = __float2half_rn(v.y);
        __half hz = __float2half_rn(v.z), hw = __float2half_rn(v.w);
        uint32_t hi0 = (uint32_t)__half_as_ushort(hx) | ((uint32_t)__half_as_ushort(hy) << 16);
        uint32_t hi1 = (uint32_t)__half_as_ushort(hz) | ((uint32_t)__half_as_ushort(hw) << 16);
        uint32_t lo0 = pack_hi_f16x2(v.x - __half2float(hx), v.y - __half2float(hy));
        uint32_t lo1 = pack_hi_f16x2(v.z - __half2float(hz), v.w - __half2float(hw));
        ((uint2*)g_w16hi)[i] = make_uint2(hi0, hi1);
        ((uint2*)g_w16lo)[i] = make_uint2(lo0, lo1);
    }
}

// ---------------------------------------------------------------------------
// Kernel A: Wh = h @ W + bW via fp16 HMMA hi/lo split; fused el/er and
// per-head er-max (CTA reduce + 1 atomicMax).
// ---------------------------------------------------------------------------
#define ASTRIDE 72
#define WH_SMEM (128 * ASTRIDE * 2 * 2 + 64 * ASTRIDE * 2 * 2)

__global__ void __launch_bounds__(256) wh_mma_kernel(
    const float* __restrict__ bW, const float* __restrict__ a_l,
    const float* __restrict__ a_r, const float* __restrict__ bA)
{
    extern __shared__ __align__(16) unsigned short sm[];
    unsigned short* Ah = sm;
    unsigned short* Al = Ah + 128 * ASTRIDE;
    unsigned short* Bh = Al + 128 * ASTRIDE;
    unsigned short* Bl = Bh + 64 * ASTRIDE;
    __shared__ float redmax[8];

    const int t    = threadIdx.x;
    const int warp = t >> 5;
    const int lane = t & 31;
    const int i0   = blockIdx.x * 128;
    const int hh   = blockIdx.y;

    const uint32_t ahB = smem_u32(Ah), alB = smem_u32(Al);
    const uint32_t bhB = smem_u32(Bh), blB = smem_u32(Bl);

    float acc[8][4];
#pragma unroll
    for (int n = 0; n < 8; n++)
#pragma unroll
        for (int j = 0; j < 4; j++) acc[n][j] = 0.f;

    const uint32_t aRow = (uint32_t)(16 * warp + (lane & 15)) * (ASTRIDE * 2) + ((lane & 16) ? 16 : 0);
    const uint32_t bRow = (uint32_t)(lane & 15) * (ASTRIDE * 2) + ((lane & 16) ? 16 : 0);

    for (int ch = 0; ch < FIN / 64; ch++) {
        const int kc = ch * 64;
        __syncthreads();
#pragma unroll
        for (int it = 0; it < 4; it++) {
            int id = t + 256 * it;
            int r = id >> 3, c = id & 7;
            size_t src = (size_t)(i0 + r) * FIN + kc + c * 8;
            *(uint4*)&Ah[r * ASTRIDE + c * 8] = *(const uint4*)(g_h16hi + src);
            *(uint4*)&Al[r * ASTRIDE + c * 8] = *(const uint4*)(g_h16lo + src);
        }
#pragma unroll
        for (int it = 0; it < 2; it++) {
            int id = t + 256 * it;
            int r = id >> 3, c = id & 7;
            size_t src = ((size_t)hh * FIN + kc + r) * FO + c * 8;
            *(uint4*)&Bh[r * ASTRIDE + c * 8] = *(const uint4*)(g_w16hi + src);
            *(uint4*)&Bl[r * ASTRIDE + c * 8] = *(const uint4*)(g_w16lo + src);
        }
        __syncthreads();

#pragma unroll
        for (int kt = 0; kt < 4; kt++) {
            uint32_t ah0, ah1, ah2, ah3, al0, al1, al2, al3;
            LDSM4(ah0, ah1, ah2, ah3, ahB + aRow + kt * 32);
            LDSM4(al0, al1, al2, al3, alB + aRow + kt * 32);
            const uint32_t kOff = (uint32_t)(16 * kt) * (ASTRIDE * 2) + bRow;
#pragma unroll
            for (int ntp = 0; ntp < 4; ntp++) {
                uint32_t bh0, bh1, bh2, bh3, bl0, bl1, bl2, bl3;
                LDSM4T(bh0, bh1, bh2, bh3, bhB + kOff + 32 * ntp);
                LDSM4T(bl0, bl1, bl2, bl3, blB + kOff + 32 * ntp);
                MMA16816F16(acc[2 * ntp],     ah0, ah1, ah2, ah3, bh0, bh1);
                MMA16816F16(acc[2 * ntp],     al0, al1, al2, al3, bh0, bh1);
                MMA16816F16(acc[2 * ntp],     ah0, ah1, ah2, ah3, bl0, bl1);
                MMA16816F16(acc[2 * ntp + 1], ah0, ah1, ah2, ah3, bh2, bh3);
                MMA16816F16(acc[2 * ntp + 1], al0, al1, al2, al3, bh2, bh3);
                MMA16816F16(acc[2 * ntp + 1], ah0, ah1, ah2, ah3, bl2, bl3);
            }
        }
    }

    // ---- epilogue: bias, store fp16 Wh, fused el/er, er-max ----
    const int q  = lane >> 2;
    const int c2 = 2 * (lane & 3);
    const int r0 = i0 + 16 * warp + q;
    const int r1 = r0 + 8;

    float dl0 = 0.f, dr0 = 0.f, dl1 = 0.f, dr1 = 0.f;
#pragma unroll
    for (int nt = 0; nt < 8; nt++) {
        int col = 8 * nt + c2;
        float2 bw = *(const float2*)(bW + hh * FO + col);
        float2 al = *(const float2*)(a_l + hh * FO + col);
        float2 ar = *(const float2*)(a_r + hh * FO + col);
        float v00 = acc[nt][0] + bw.x, v01 = acc[nt][1] + bw.y;
        float v10 = acc[nt][2] + bw.x, v11 = acc[nt][3] + bw.y;
        *(uint32_t*)(g_wh16 + ((size_t)hh * NN + r0) * FO + col) = pack_hi_f16x2(v00, v01);
        *(uint32_t*)(g_wh16 + ((size_t)hh * NN + r1) * FO + col) = pack_hi_f16x2(v10, v11);
        dl0 += v00 * al.x + v01 * al.y;
        dr0 += v00 * ar.x + v01 * ar.y;
        dl1 += v10 * al.x + v11 * al.y;
        dr1 += v10 * ar.x + v11 * ar.y;
    }
#pragma unroll
    for (int off = 1; off < 4; off <<= 1) {
        dl0 += __shfl_xor_sync(0xffffffffu, dl0, off);
        dr0 += __shfl_xor_sync(0xffffffffu, dr0, off);
        dl1 += __shfl_xor_sync(0xffffffffu, dl1, off);
        dr1 += __shfl_xor_sync(0xffffffffu, dr1, off);
    }
    float er0s = dr0 * LOG2E, er1s = dr1 * LOG2E;
    if ((lane & 3) == 0) {
        float ba = bA[hh];
        g_el[hh * NN + r0] = (dl0 + ba) * LOG2E;
        g_er[hh * NN + r0] = er0s;
        g_el[hh * NN + r1] = (dl1 + ba) * LOG2E;
        g_er[hh * NN + r1] = er1s;
    }
    // warp max of er over its 16 rows -> smem -> one atomic per CTA
    float wm = fmaxf(er0s, er1s);
#pragma unroll
    for (int off = 4; off < 32; off <<= 1)
        wm = fmaxf(wm, __shfl_xor_sync(0xffffffffu, wm, off));
    if (lane == 0) redmax[warp] = wm;
    __syncthreads();
    if (t == 0) {
        float m = redmax[0];
#pragma unroll
        for (int w = 1; w < 8; w++) m = fmaxf(m, redmax[w]);
        atomicMax(&g_ermax_enc[hh], f2ord(m));
    }
}

// ---------------------------------------------------------------------------
// Kernel A2: mask -> bitmap
// ---------------------------------------------------------------------------
__global__ void __launch_bounds__(256) mask_bits_kernel(const int* __restrict__ mask)
{
    int gw   = (blockIdx.x * 256 + threadIdx.x) >> 5;
    int lane = threadIdx.x & 31;
    int row  = gw >> 7;
    int wd   = gw & (NWORD - 1);
    int m = mask[(size_t)row * NN + wd * 32 + lane];
    uint32_t b = __ballot_sync(0xffffffffu, m > 0);
    if (lane == 0) g_bits[gw] = b;
}

// ---------------------------------------------------------------------------
// Kernel C: fp16 HMMA flash-GAT (R6-proven f32 score path).
// Score: with el' = el - c and d = (ALPHA-1)*c,
//   lrelu(el+er) - c = max(x', ALPHA*x' + d),  x' = el' + er.
// Denominator: one MMA per kt against a constant all-ones B fragment.
// ---------------------------------------------------------------------------
__device__ __forceinline__ float elu(float v) {
    return v > 0.f ? v : (__expf(v) - 1.f);
}

__device__ __forceinline__ uint32_t pscore2(float2 ed, float2 er, uint32_t b2) {
    float x0 = ed.x + er.x;
    float a0 = fmaxf(x0, fmaf(ALPHA, x0, ed.y));
    float x1 = ed.x + er.y;
    float a1 = fmaxf(x1, fmaf(ALPHA, x1, ed.y));
    uint32_t ph, pe;
    asm("cvt.rn.f16x2.f32 %0, %1, %2;" : "=r"(ph) : "f"(a1), "f"(a0));
    asm("ex2.approx.f16x2 %0, %1;" : "=r"(pe) : "r"(ph));
    uint32_t msk = ((b2 & 1u) ? 0x0000FFFFu : 0u) | ((b2 & 2u) ? 0xFFFF0000u : 0u);
    return pe & msk;
}

#define BSTRIDE 72

__global__ void __launch_bounds__(256, 2) gat_attn_mma_kernel(float* __restrict__ out)
{
    __shared__ __align__(16) unsigned short Bs[2][64 * BSTRIDE];
    __shared__ float2 els2[128];

    const int t    = threadIdx.x;
    const int warp = t >> 5;
    const int lane = t & 31;
    const int i0   = blockIdx.x * 128;
    const int hh   = blockIdx.y;

    if (t < 128) {
        float e = g_el[hh * NN + i0 + t];
        float z = e + ord2f(g_ermax_enc[hh]);
        float c = fmaxf(z, ALPHA * z);
        els2[t] = make_float2(e - c, (ALPHA - 1.f) * c);
    }

    const int q  = lane >> 2;
    const int c2 = 2 * (lane & 3);
    const int rw0 = 16 * warp + q;

    const float* erb = g_er + hh * NN + c2;
    const unsigned short* gwh = g_wh16 + (size_t)hh * NN * FO;
    const uint32_t* bitrow = g_bits + (size_t)(i0 + 16 * warp + (lane >> 1)) * NWORD + (lane & 1);

    const uint32_t bBase = smem_u32(Bs);
    const uint32_t lrowOff = (uint32_t)(lane & 15) * (BSTRIDE * 2) + ((lane & 16) ? 16 : 0);

    const int lk0 = t >> 3, lc0 = t & 7;
    const int lk1 = (t + 256) >> 3, lc1 = t & 7;

    float acc[8][4];
#pragma unroll
    for (int n = 0; n < 8; n++)
#pragma unroll
        for (int j = 0; j < 4; j++) acc[n][j] = 0.f;
    float accd[4] = {0.f, 0.f, 0.f, 0.f};
    const uint32_t ONES = 0x3C003C00u;

    {
        uint4 va = *(const uint4*)(gwh + (size_t)lk0 * FO + lc0 * 8);
        uint4 vb = *(const uint4*)(gwh + (size_t)lk1 * FO + lc1 * 8);
        *(uint4*)&Bs[0][lk0 * BSTRIDE + lc0 * 8] = va;
        *(uint4*)&Bs[0][lk1 * BSTRIDE + lc1 * 8] = vb;
    }
    __syncthreads();

    const float2 ec0 = els2[rw0];
    const float2 ec1 = els2[rw0 + 8];

    for (int tile = 0; tile < NN / 64; tile++) {
        const int j0 = tile * 64;
        const int cur = tile & 1;

        uint32_t bv = bitrow[(uint32_t)(j0 >> 5)];
        uint32_t w00 = __shfl_sync(0xffffffffu, bv, 2 * q);
        uint32_t w01 = __shfl_sync(0xffffffffu, bv, 2 * q + 1);
        uint32_t w10 = __shfl_sync(0xffffffffu, bv, 2 * q + 16);
        uint32_t w11 = __shfl_sync(0xffffffffu, bv, 2 * q + 17);

        uint4 na, nb;
        if (tile < NN / 64 - 1) {
            const unsigned short* src = gwh + (size_t)(j0 + 64) * FO;
            na = *(const uint4*)(src + (size_t)lk0 * FO + lc0 * 8);
            nb = *(const uint4*)(src + (size_t)lk1 * FO + lc1 * 8);
        }

        const uint32_t bufOff = bBase + cur * (64 * BSTRIDE * 2) + lrowOff;

#pragma unroll
        for (int kt = 0; kt < 4; kt++) {
            const int jb = j0 + 16 * kt;
            float2 e0 = *(const float2*)(erb + jb);
            float2 e1 = *(const float2*)(erb + jb + 8);

            uint32_t wr0 = (kt < 2) ? w00 : w01;
            uint32_t wr1 = (kt < 2) ? w10 : w11;
            const int sb = (kt & 1) * 16;
            uint32_t v0 = wr0 >> (sb + c2);
            uint32_t v1 = wr1 >> (sb + c2);

            uint32_t a0 = pscore2(ec0, e0, v0 & 3u);
            uint32_t a1 = pscore2(ec1, e0, v1 & 3u);
            uint32_t a2 = pscore2(ec0, e1, (v0 >> 8) & 3u);
            uint32_t a3 = pscore2(ec1, e1, (v1 >> 8) & 3u);

            const uint32_t kOff = bufOff + (uint32_t)(16 * kt) * (BSTRIDE * 2);
#pragma unroll
            for (int ntp = 0; ntp < 4; ntp++) {
                uint32_t b0, b1, b2, b3;
                LDSM4T(b0, b1, b2, b3, kOff + 32 * ntp);
                MMA16816F16(acc[2 * ntp],     a0, a1, a2, a3, b0, b1);
                MMA16816F16(acc[2 * ntp + 1], a0, a1, a2, a3, b2, b3);
            }
            MMA16816F16(accd, a0, a1, a2, a3, ONES, ONES);
        }

        if (tile < NN / 64 - 1) {
            unsigned short* dst = &Bs[cur ^ 1][0];
            *(uint4*)&dst[lk0 * BSTRIDE + lc0 * 8] = na;
            *(uint4*)&dst[lk1 * BSTRIDE + lc1 * 8] = nb;
        }
        __syncthreads();
    }

    const float inv0 = 1.f / accd[0];
    const float inv1 = 1.f / accd[2];

    float* ob0 = out + (size_t)(i0 + rw0) * OUTW + hh * FO + c2;
    float* ob1 = ob0 + (size_t)8 * OUTW;
#pragma unroll
    for (int nt = 0; nt < 8; nt++) {
        float2 v0 = make_float2(elu(acc[nt][0] * inv0), elu(acc[nt][1] * inv0));
        float2 v1 = make_float2(elu(acc[nt][2] * inv1), elu(acc[nt][3] * inv1));
        *(float2*)(ob0 + 8 * nt) = v0;
        *(float2*)(ob1 + 8 * nt) = v1;
    }
}

// ---------------------------------------------------------------------------
extern "C" void kernel_launch(void* const* d_in, const int* in_sizes, int n_in,
                              void* d_out, int out_size)
{
    const float* h    = (const float*)d_in[0];  // [N, FIN]
    const int*   mask = (const int*)  d_in[1];  // [N, N]
    const float* W    = (const float*)d_in[2];  // [H, FIN, FO]
    const float* bW   = (const float*)d_in[3];  // [H, FO]
    const float* a_l  = (const float*)d_in[4];  // [H, FO]
    const float* a_r  = (const float*)d_in[5];  // [H, FO]
    const float* bA   = (const float*)d_in[6];  // [H]
    float* out = (float*)d_out;                 // [N, H*FO]

    cudaFuncSetAttribute(wh_mma_kernel,
                         cudaFuncAttributeMaxDynamicSharedMemorySize, WH_SMEM);

    prep_kernel<<<1024, 256>>>(h, W);
    wh_mma_kernel<<<dim3(NN / 128, NH), 256, WH_SMEM>>>(bW, a_l, a_r, bA);
    mask_bits_kernel<<<NN * NWORD / 8, 256>>>(mask);
    gat_attn_mma_kernel<<<dim3(NN / 128, NH), 256>>>(out);
}

// round 9
// speedup vs baseline: 1.4975x; 1.0406x over previous
#include <cuda_runtime.h>
#include <cuda_fp16.h>
#include <cstdint>

#define NN 4096
#define FIN 512
#define FO 64
#define NH 8
#define ALPHA 0.2f
#define OUTW (NH * FO)  /* 512 */
#define LOG2E 1.4426950408889634f
#define NWORD (NN / 32)  /* 128 */

// ---------------------------------------------------------------------------
// Scratch (static device globals)
// ---------------------------------------------------------------------------
__device__ unsigned short g_h16hi[NN * FIN];     // fp16 hi of h, [n][k]
__device__ unsigned short g_h16lo[NN * FIN];     // fp16 lo of h, [n][k]
__device__ unsigned short g_w16hi[NH * FIN * FO];// fp16 hi of W, [h][k][n]
__device__ unsigned short g_w16lo[NH * FIN * FO];
__device__ unsigned short g_wh16[NH * NN * FO];  // fp16 Wh, [h][n][o]
__device__ float g_el[NH * NN];                  // el * log2e (incl bA)
__device__ float g_er[NH * NN];                  // er * log2e
__device__ unsigned int g_ermax_enc[NH];         // order-preserving encoded max
__device__ uint32_t g_bits[NN * NWORD];          // mask bitmap [i][j/32]

__device__ __forceinline__ uint32_t smem_u32(const void* p) {
    uint32_t a;
    asm("{ .reg .u64 t; cvta.to.shared.u64 t, %1; cvt.u32.u64 %0, t; }" : "=r"(a) : "l"(p));
    return a;
}

// order-preserving float <-> uint encoding (for atomicMax on any-sign floats)
__device__ __forceinline__ unsigned int f2ord(float f) {
    unsigned int u = __float_as_uint(f);
    return (u & 0x80000000u) ? ~u : (u | 0x80000000u);
}
__device__ __forceinline__ float ord2f(unsigned int k) {
    unsigned int u = (k & 0x80000000u) ? (k & 0x7FFFFFFFu) : ~k;
    return __uint_as_float(u);
}

#define MMA16816F16(acc, a0, a1, a2, a3, b0, b1) \
    asm volatile("mma.sync.aligned.m16n8k16.row.col.f32.f16.f16.f32 " \
        "{%0,%1,%2,%3}, {%4,%5,%6,%7}, {%8,%9}, {%0,%1,%2,%3};" \
        : "+f"((acc)[0]), "+f"((acc)[1]), "+f"((acc)[2]), "+f"((acc)[3]) \
        : "r"(a0), "r"(a1), "r"(a2), "r"(a3), "r"(b0), "r"(b1))

#define LDSM4T(r0, r1, r2, r3, a) \
    asm volatile("ldmatrix.sync.aligned.m8n8.x4.trans.shared.b16 {%0,%1,%2,%3}, [%4];" \
        : "=r"(r0), "=r"(r1), "=r"(r2), "=r"(r3) : "r"(a))

#define LDSM4(r0, r1, r2, r3, a) \
    asm volatile("ldmatrix.sync.aligned.m8n8.x4.shared.b16 {%0,%1,%2,%3}, [%4];" \
        : "=r"(r0), "=r"(r1), "=r"(r2), "=r"(r3) : "r"(a))

__device__ __forceinline__ uint32_t pack_hi_f16x2(float a, float b) {
    uint32_t r;
    asm("cvt.rn.f16x2.f32 %0, %1, %2;" : "=r"(r) : "f"(b), "f"(a));
    return r;
}

// ---------------------------------------------------------------------------
// Kernel P: convert h and W to fp16 hi/lo; init ermax accumulators.
// ---------------------------------------------------------------------------
__global__ void __launch_bounds__(256) prep_kernel(
    const float* __restrict__ h, const float* __restrict__ W)
{
    if (blockIdx.x == 0 && threadIdx.x < NH)
        g_ermax_enc[threadIdx.x] = 0u;  // below every encoded float

    const int stride = gridDim.x * 256;
    for (int i = blockIdx.x * 256 + threadIdx.x; i < NN * FIN / 4; i += stride) {
        float4 v = ((const float4*)h)[i];
        __half hx = __float2half_rn(v.x), hy = __float2half_rn(v.y);
        __half hz = __float2half_rn(v.z), hw = __float2half_rn(v.w);
        uint32_t hi0 = (uint32_t)__half_as_ushort(hx) | ((uint32_t)__half_as_ushort(hy) << 16);
        uint32_t hi1 = (uint32_t)__half_as_ushort(hz) | ((uint32_t)__half_as_ushort(hw) << 16);
        uint32_t lo0 = pack_hi_f16x2(v.x - __half2float(hx), v.y - __half2float(hy));
        uint32_t lo1 = pack_hi_f16x2(v.z - __half2float(hz), v.w - __half2float(hw));
        ((uint2*)g_h16hi)[i] = make_uint2(hi0, hi1);
        ((uint2*)g_h16lo)[i] = make_uint2(lo0, lo1);
    }
    for (int i = blockIdx.x * 256 + threadIdx.x; i < NH * FIN * FO / 4; i += stride) {
        float4 v = ((const float4*)W)[i];
        __half hx = __float2half_rn(v.x), hy = __float2half_rn(v.y);
        __half hz = __float2half_rn(v.z), hw = __float2half_rn(v.w);
        uint32_t hi0 = (uint32_t)__half_as_ushort(hx) | ((uint32_t)__half_as_ushort(hy) << 16);
        uint32_t hi1 = (uint32_t)__half_as_ushort(hz) | ((uint32_t)__half_as_ushort(hw) << 16);
        uint32_t lo0 = pack_hi_f16x2(v.x - __half2float(hx), v.y - __half2float(hy));
        uint32_t lo1 = pack_hi_f16x2(v.z - __half2float(hz), v.w - __half2float(hw));
        ((uint2*)g_w16hi)[i] = make_uint2(hi0, hi1);
        ((uint2*)g_w16lo)[i] = make_uint2(lo0, lo1);
    }
}

// ---------------------------------------------------------------------------
// Kernel A: Wh = h @ W + bW via fp16 HMMA hi/lo split; fused el/er and
// per-head er-max (CTA reduce + 1 atomicMax).
// ---------------------------------------------------------------------------
#define ASTRIDE 72
#define WH_SMEM (128 * ASTRIDE * 2 * 2 + 64 * ASTRIDE * 2 * 2)

__global__ void __launch_bounds__(256) wh_mma_kernel(
    const float* __restrict__ bW, const float* __restrict__ a_l,
    const float* __restrict__ a_r, const float* __restrict__ bA)
{
    extern __shared__ __align__(16) unsigned short sm[];
    unsigned short* Ah = sm;
    unsigned short* Al = Ah + 128 * ASTRIDE;
    unsigned short* Bh = Al + 128 * ASTRIDE;
    unsigned short* Bl = Bh + 64 * ASTRIDE;
    __shared__ float redmax[8];

    const int t    = threadIdx.x;
    const int warp = t >> 5;
    const int lane = t & 31;
    const int i0   = blockIdx.x * 128;
    const int hh   = blockIdx.y;

    const uint32_t ahB = smem_u32(Ah), alB = smem_u32(Al);
    const uint32_t bhB = smem_u32(Bh), blB = smem_u32(Bl);

    float acc[8][4];
#pragma unroll
    for (int n = 0; n < 8; n++)
#pragma unroll
        for (int j = 0; j < 4; j++) acc[n][j] = 0.f;

    const uint32_t aRow = (uint32_t)(16 * warp + (lane & 15)) * (ASTRIDE * 2) + ((lane & 16) ? 16 : 0);
    const uint32_t bRow = (uint32_t)(lane & 15) * (ASTRIDE * 2) + ((lane & 16) ? 16 : 0);

    for (int ch = 0; ch < FIN / 64; ch++) {
        const int kc = ch * 64;
        __syncthreads();
#pragma unroll
        for (int it = 0; it < 4; it++) {
            int id = t + 256 * it;
            int r = id >> 3, c = id & 7;
            size_t src = (size_t)(i0 + r) * FIN + kc + c * 8;
            *(uint4*)&Ah[r * ASTRIDE + c * 8] = *(const uint4*)(g_h16hi + src);
            *(uint4*)&Al[r * ASTRIDE + c * 8] = *(const uint4*)(g_h16lo + src);
        }
#pragma unroll
        for (int it = 0; it < 2; it++) {
            int id = t + 256 * it;
            int r = id >> 3, c = id & 7;
            size_t src = ((size_t)hh * FIN + kc + r) * FO + c * 8;
            *(uint4*)&Bh[r * ASTRIDE + c * 8] = *(const uint4*)(g_w16hi + src);
            *(uint4*)&Bl[r * ASTRIDE + c * 8] = *(const uint4*)(g_w16lo + src);
        }
        __syncthreads();

#pragma unroll
        for (int kt = 0; kt < 4; kt++) {
            uint32_t ah0, ah1, ah2, ah3, al0, al1, al2, al3;
            LDSM4(ah0, ah1, ah2, ah3, ahB + aRow + kt * 32);
            LDSM4(al0, al1, al2, al3, alB + aRow + kt * 32);
            const uint32_t kOff = (uint32_t)(16 * kt) * (ASTRIDE * 2) + bRow;
#pragma unroll
            for (int ntp = 0; ntp < 4; ntp++) {
                uint32_t bh0, bh1, bh2, bh3, bl0, bl1, bl2, bl3;
                LDSM4T(bh0, bh1, bh2, bh3, bhB + kOff + 32 * ntp);
                LDSM4T(bl0, bl1, bl2, bl3, blB + kOff + 32 * ntp);
                MMA16816F16(acc[2 * ntp],     ah0, ah1, ah2, ah3, bh0, bh1);
                MMA16816F16(acc[2 * ntp],     al0, al1, al2, al3, bh0, bh1);
                MMA16816F16(acc[2 * ntp],     ah0, ah1, ah2, ah3, bl0, bl1);
                MMA16816F16(acc[2 * ntp + 1], ah0, ah1, ah2, ah3, bh2, bh3);
                MMA16816F16(acc[2 * ntp + 1], al0, al1, al2, al3, bh2, bh3);
                MMA16816F16(acc[2 * ntp + 1], ah0, ah1, ah2, ah3, bl2, bl3);
            }
        }
    }

    // ---- epilogue: bias, store fp16 Wh, fused el/er, er-max ----
    const int q  = lane >> 2;
    const int c2 = 2 * (lane & 3);
    const int r0 = i0 + 16 * warp + q;
    const int r1 = r0 + 8;

    float dl0 = 0.f, dr0 = 0.f, dl1 = 0.f, dr1 = 0.f;
#pragma unroll
    for (int nt = 0; nt < 8; nt++) {
        int col = 8 * nt + c2;
        float2 bw = *(const float2*)(bW + hh * FO + col);
        float2 al = *(const float2*)(a_l + hh * FO + col);
        float2 ar = *(const float2*)(a_r + hh * FO + col);
        float v00 = acc[nt][0] + bw.x, v01 = acc[nt][1] + bw.y;
        float v10 = acc[nt][2] + bw.x, v11 = acc[nt][3] + bw.y;
        *(uint32_t*)(g_wh16 + ((size_t)hh * NN + r0) * FO + col) = pack_hi_f16x2(v00, v01);
        *(uint32_t*)(g_wh16 + ((size_t)hh * NN + r1) * FO + col) = pack_hi_f16x2(v10, v11);
        dl0 += v00 * al.x + v01 * al.y;
        dr0 += v00 * ar.x + v01 * ar.y;
        dl1 += v10 * al.x + v11 * al.y;
        dr1 += v10 * ar.x + v11 * ar.y;
    }
#pragma unroll
    for (int off = 1; off < 4; off <<= 1) {
        dl0 += __shfl_xor_sync(0xffffffffu, dl0, off);
        dr0 += __shfl_xor_sync(0xffffffffu, dr0, off);
        dl1 += __shfl_xor_sync(0xffffffffu, dl1, off);
        dr1 += __shfl_xor_sync(0xffffffffu, dr1, off);
    }
    float er0s = dr0 * LOG2E, er1s = dr1 * LOG2E;
    if ((lane & 3) == 0) {
        float ba = bA[hh];
        g_el[hh * NN + r0] = (dl0 + ba) * LOG2E;
        g_er[hh * NN + r0] = er0s;
        g_el[hh * NN + r1] = (dl1 + ba) * LOG2E;
        g_er[hh * NN + r1] = er1s;
    }
    // warp max of er over its 16 rows -> smem -> one atomic per CTA
    float wm = fmaxf(er0s, er1s);
#pragma unroll
    for (int off = 4; off < 32; off <<= 1)
        wm = fmaxf(wm, __shfl_xor_sync(0xffffffffu, wm, off));
    if (lane == 0) redmax[warp] = wm;
    __syncthreads();
    if (t == 0) {
        float m = redmax[0];
#pragma unroll
        for (int w = 1; w < 8; w++) m = fmaxf(m, redmax[w]);
        atomicMax(&g_ermax_enc[hh], f2ord(m));
    }
}

// ---------------------------------------------------------------------------
// Kernel A2: mask -> bitmap
// ---------------------------------------------------------------------------
__global__ void __launch_bounds__(256) mask_bits_kernel(const int* __restrict__ mask)
{
    int gw   = (blockIdx.x * 256 + threadIdx.x) >> 5;
    int lane = threadIdx.x & 31;
    int row  = gw >> 7;
    int wd   = gw & (NWORD - 1);
    int m = mask[(size_t)row * NN + wd * 32 + lane];
    uint32_t b = __ballot_sync(0xffffffffu, m > 0);
    if (lane == 0) g_bits[gw] = b;
}

// ---------------------------------------------------------------------------
// Kernel C: fp16 HMMA flash-GAT. er staged in smem; bits prefetched one tile
// ahead; f32 score path (R6/R8-proven).
// ---------------------------------------------------------------------------
__device__ __forceinline__ float elu(float v) {
    return v > 0.f ? v : (__expf(v) - 1.f);
}

__device__ __forceinline__ uint32_t pscore2(float2 ed, float2 er, uint32_t b2) {
    float x0 = ed.x + er.x;
    float a0 = fmaxf(x0, fmaf(ALPHA, x0, ed.y));
    float x1 = ed.x + er.y;
    float a1 = fmaxf(x1, fmaf(ALPHA, x1, ed.y));
    uint32_t ph, pe;
    asm("cvt.rn.f16x2.f32 %0, %1, %2;" : "=r"(ph) : "f"(a1), "f"(a0));
    asm("ex2.approx.f16x2 %0, %1;" : "=r"(pe) : "r"(ph));
    uint32_t msk = ((b2 & 1u) ? 0x0000FFFFu : 0u) | ((b2 & 2u) ? 0xFFFF0000u : 0u);
    return pe & msk;
}

#define BSTRIDE 72

__global__ void __launch_bounds__(256, 2) gat_attn_mma_kernel(float* __restrict__ out)
{
    __shared__ __align__(16) unsigned short Bs[2][64 * BSTRIDE];
    __shared__ float2 els2[128];
    __shared__ __align__(16) float ers[NN];   // 16KB: the head's er row

    const int t    = threadIdx.x;
    const int warp = t >> 5;
    const int lane = t & 31;
    const int i0   = blockIdx.x * 128;
    const int hh   = blockIdx.y;

    // stage er into smem (coalesced float4)
    {
        const float4* src = (const float4*)(g_er + hh * NN);
#pragma unroll
        for (int it = 0; it < NN / 4 / 256; it++)
            ((float4*)ers)[t + 256 * it] = src[t + 256 * it];
    }

    if (t < 128) {
        float e = g_el[hh * NN + i0 + t];
        float z = e + ord2f(g_ermax_enc[hh]);
        float c = fmaxf(z, ALPHA * z);
        els2[t] = make_float2(e - c, (ALPHA - 1.f) * c);
    }

    const int q  = lane >> 2;
    const int c2 = 2 * (lane & 3);
    const int rw0 = 16 * warp + q;

    const unsigned short* gwh = g_wh16 + (size_t)hh * NN * FO;
    const uint32_t* bitrow = g_bits + (size_t)(i0 + 16 * warp + (lane >> 1)) * NWORD + (lane & 1);

    const uint32_t bBase = smem_u32(Bs);
    const uint32_t lrowOff = (uint32_t)(lane & 15) * (BSTRIDE * 2) + ((lane & 16) ? 16 : 0);

    const int lk0 = t >> 3, lc0 = t & 7;
    const int lk1 = (t + 256) >> 3, lc1 = t & 7;

    float acc[8][4];
#pragma unroll
    for (int n = 0; n < 8; n++)
#pragma unroll
        for (int j = 0; j < 4; j++) acc[n][j] = 0.f;
    float accd[4] = {0.f, 0.f, 0.f, 0.f};
    const uint32_t ONES = 0x3C003C00u;

    {
        uint4 va = *(const uint4*)(gwh + (size_t)lk0 * FO + lc0 * 8);
        uint4 vb = *(const uint4*)(gwh + (size_t)lk1 * FO + lc1 * 8);
        *(uint4*)&Bs[0][lk0 * BSTRIDE + lc0 * 8] = va;
        *(uint4*)&Bs[0][lk1 * BSTRIDE + lc1 * 8] = vb;
    }
    uint32_t bvNext = bitrow[0];   // bits for tile 0
    __syncthreads();

    const float2 ec0 = els2[rw0];
    const float2 ec1 = els2[rw0 + 8];

    for (int tile = 0; tile < NN / 64; tile++) {
        const int j0 = tile * 64;
        const int cur = tile & 1;

        uint32_t bv = bvNext;
        if (tile < NN / 64 - 1) bvNext = bitrow[(uint32_t)((j0 >> 5) + 2)];

        uint32_t w00 = __shfl_sync(0xffffffffu, bv, 2 * q);
        uint32_t w01 = __shfl_sync(0xffffffffu, bv, 2 * q + 1);
        uint32_t w10 = __shfl_sync(0xffffffffu, bv, 2 * q + 16);
        uint32_t w11 = __shfl_sync(0xffffffffu, bv, 2 * q + 17);

        uint4 na, nb;
        if (tile < NN / 64 - 1) {
            const unsigned short* src = gwh + (size_t)(j0 + 64) * FO;
            na = *(const uint4*)(src + (size_t)lk0 * FO + lc0 * 8);
            nb = *(const uint4*)(src + (size_t)lk1 * FO + lc1 * 8);
        }

        const uint32_t bufOff = bBase + cur * (64 * BSTRIDE * 2) + lrowOff;

#pragma unroll
        for (int kt = 0; kt < 4; kt++) {
            const int jb = j0 + 16 * kt + c2;
            float2 e0 = *(const float2*)(ers + jb);
            float2 e1 = *(const float2*)(ers + jb + 8);

            uint32_t wr0 = (kt < 2) ? w00 : w01;
            uint32_t wr1 = (kt < 2) ? w10 : w11;
            const int sb = (kt & 1) * 16;
            uint32_t v0 = wr0 >> (sb + c2);
            uint32_t v1 = wr1 >> (sb + c2);

            uint32_t a0 = pscore2(ec0, e0, v0 & 3u);
            uint32_t a1 = pscore2(ec1, e0, v1 & 3u);
            uint32_t a2 = pscore2(ec0, e1, (v0 >> 8) & 3u);
            uint32_t a3 = pscore2(ec1, e1, (v1 >> 8) & 3u);

            const uint32_t kOff = bufOff + (uint32_t)(16 * kt) * (BSTRIDE * 2);
#pragma unroll
            for (int ntp = 0; ntp < 4; ntp++) {
                uint32_t b0, b1, b2, b3;
                LDSM4T(b0, b1, b2, b3, kOff + 32 * ntp);
                MMA16816F16(acc[2 * ntp],     a0, a1, a2, a3, b0, b1);
                MMA16816F16(acc[2 * ntp + 1], a0, a1, a2, a3, b2, b3);
            }
            MMA16816F16(accd, a0, a1, a2, a3, ONES, ONES);
        }

        if (tile < NN / 64 - 1) {
            unsigned short* dst = &Bs[cur ^ 1][0];
            *(uint4*)&dst[lk0 * BSTRIDE + lc0 * 8] = na;
            *(uint4*)&dst[lk1 * BSTRIDE + lc1 * 8] = nb;
        }
        __syncthreads();
    }

    const float inv0 = 1.f / accd[0];
    const float inv1 = 1.f / accd[2];

    float* ob0 = out + (size_t)(i0 + rw0) * OUTW + hh * FO + c2;
    float* ob1 = ob0 + (size_t)8 * OUTW;
#pragma unroll
    for (int nt = 0; nt < 8; nt++) {
        float2 v0 = make_float2(elu(acc[nt][0] * inv0), elu(acc[nt][1] * inv0));
        float2 v1 = make_float2(elu(acc[nt][2] * inv1), elu(acc[nt][3] * inv1));
        *(float2*)(ob0 + 8 * nt) = v0;
        *(float2*)(ob1 + 8 * nt) = v1;
    }
}

// ---------------------------------------------------------------------------
extern "C" void kernel_launch(void* const* d_in, const int* in_sizes, int n_in,
                              void* d_out, int out_size)
{
    const float* h    = (const float*)d_in[0];  // [N, FIN]
    const int*   mask = (const int*)  d_in[1];  // [N, N]
    const float* W    = (const float*)d_in[2];  // [H, FIN, FO]
    const float* bW   = (const float*)d_in[3];  // [H, FO]
    const float* a_l  = (const float*)d_in[4];  // [H, FO]
    const float* a_r  = (const float*)d_in[5];  // [H, FO]
    const float* bA   = (const float*)d_in[6];  // [H]
    float* out = (float*)d_out;                 // [N, H*FO]

    cudaFuncSetAttribute(wh_mma_kernel,
                         cudaFuncAttributeMaxDynamicSharedMemorySize, WH_SMEM);

    prep_kernel<<<1024, 256>>>(h, W);
    wh_mma_kernel<<<dim3(NN / 128, NH), 256, WH_SMEM>>>(bW, a_l, a_r, bA);
    mask_bits_kernel<<<NN * NWORD / 8, 256>>>(mask);
    gat_attn_mma_kernel<<<dim3(NN / 128, NH), 256>>>(out);
}

// round 10
// speedup vs baseline: 1.5998x; 1.0683x over previous
#include <cuda_runtime.h>
#include <cuda_fp16.h>
#include <cstdint>

#define NN 4096
#define FIN 512
#define FO 64
#define NH 8
#define ALPHA 0.2f
#define OUTW (NH * FO)  /* 512 */
#define LOG2E 1.4426950408889634f
#define NWORD (NN / 32)  /* 128 */

// ---------------------------------------------------------------------------
// Scratch (static device globals)
// ---------------------------------------------------------------------------
__device__ unsigned short g_h16hi[NN * FIN];     // fp16 hi of h, [n][k]
__device__ unsigned short g_h16lo[NN * FIN];     // fp16 lo of h, [n][k]
__device__ unsigned short g_w16hi[NH * FIN * FO];// fp16 hi of W, [h][k][n]
__device__ unsigned short g_w16lo[NH * FIN * FO];
__device__ unsigned short g_wh16[NH * NN * FO];  // fp16 Wh, [h][n][o]
__device__ float g_el[NH * NN];                  // el * log2e (incl bA)
__device__ float g_er[NH * NN];                  // er * log2e
__device__ unsigned int g_ermax_enc[NH];         // order-preserving encoded max
__device__ uint32_t g_bits[NN * NWORD];          // mask bitmap [i][j/32]

__device__ __forceinline__ uint32_t smem_u32(const void* p) {
    uint32_t a;
    asm("{ .reg .u64 t; cvta.to.shared.u64 t, %1; cvt.u32.u64 %0, t; }" : "=r"(a) : "l"(p));
    return a;
}

// order-preserving float <-> uint encoding (for atomicMax on any-sign floats)
__device__ __forceinline__ unsigned int f2ord(float f) {
    unsigned int u = __float_as_uint(f);
    return (u & 0x80000000u) ? ~u : (u | 0x80000000u);
}
__device__ __forceinline__ float ord2f(unsigned int k) {
    unsigned int u = (k & 0x80000000u) ? (k & 0x7FFFFFFFu) : ~k;
    return __uint_as_float(u);
}

#define MMA16816F16(acc, a0, a1, a2, a3, b0, b1) \
    asm volatile("mma.sync.aligned.m16n8k16.row.col.f32.f16.f16.f32 " \
        "{%0,%1,%2,%3}, {%4,%5,%6,%7}, {%8,%9}, {%0,%1,%2,%3};" \
        : "+f"((acc)[0]), "+f"((acc)[1]), "+f"((acc)[2]), "+f"((acc)[3]) \
        : "r"(a0), "r"(a1), "r"(a2), "r"(a3), "r"(b0), "r"(b1))

#define LDSM4T(r0, r1, r2, r3, a) \
    asm volatile("ldmatrix.sync.aligned.m8n8.x4.trans.shared.b16 {%0,%1,%2,%3}, [%4];" \
        : "=r"(r0), "=r"(r1), "=r"(r2), "=r"(r3) : "r"(a))

#define LDSM4(r0, r1, r2, r3, a) \
    asm volatile("ldmatrix.sync.aligned.m8n8.x4.shared.b16 {%0,%1,%2,%3}, [%4];" \
        : "=r"(r0), "=r"(r1), "=r"(r2), "=r"(r3) : "r"(a))

__device__ __forceinline__ uint32_t pack_hi_f16x2(float a, float b) {
    uint32_t r;
    asm("cvt.rn.f16x2.f32 %0, %1, %2;" : "=r"(r) : "f"(b), "f"(a));
    return r;
}

// ---------------------------------------------------------------------------
// Kernel P: convert h and W to fp16 hi/lo; mask -> bitmap; init ermax.
// ---------------------------------------------------------------------------
__global__ void __launch_bounds__(256) prep_kernel(
    const float* __restrict__ h, const float* __restrict__ W,
    const int* __restrict__ mask)
{
    if (blockIdx.x == 0 && threadIdx.x < NH)
        g_ermax_enc[threadIdx.x] = 0u;  // below every encoded float

    const int stride = gridDim.x * 256;
    for (int i = blockIdx.x * 256 + threadIdx.x; i < NN * FIN / 4; i += stride) {
        float4 v = ((const float4*)h)[i];
        __half hx = __float2half_rn(v.x), hy = __float2half_rn(v.y);
        __half hz = __float2half_rn(v.z), hw = __float2half_rn(v.w);
        uint32_t hi0 = (uint32_t)__half_as_ushort(hx) | ((uint32_t)__half_as_ushort(hy) << 16);
        uint32_t hi1 = (uint32_t)__half_as_ushort(hz) | ((uint32_t)__half_as_ushort(hw) << 16);
        uint32_t lo0 = pack_hi_f16x2(v.x - __half2float(hx), v.y - __half2float(hy));
        uint32_t lo1 = pack_hi_f16x2(v.z - __half2float(hz), v.w - __half2float(hw));
        ((uint2*)g_h16hi)[i] = make_uint2(hi0, hi1);
        ((uint2*)g_h16lo)[i] = make_uint2(lo0, lo1);
    }
    for (int i = blockIdx.x * 256 + threadIdx.x; i < NH * FIN * FO / 4; i += stride) {
        float4 v = ((const float4*)W)[i];
        __half hx = __float2half_rn(v.x), hy = __float2half_rn(v.y);
        __half hz = __float2half_rn(v.z), hw = __float2half_rn(v.w);
        uint32_t hi0 = (uint32_t)__half_as_ushort(hx) | ((uint32_t)__half_as_ushort(hy) << 16);
        uint32_t hi1 = (uint32_t)__half_as_ushort(hz) | ((uint32_t)__half_as_ushort(hw) << 16);
        uint32_t lo0 = pack_hi_f16x2(v.x - __half2float(hx), v.y - __half2float(hy));
        uint32_t lo1 = pack_hi_f16x2(v.z - __half2float(hz), v.w - __half2float(hw));
        ((uint2*)g_w16hi)[i] = make_uint2(hi0, hi1);
        ((uint2*)g_w16lo)[i] = make_uint2(lo0, lo1);
    }
    // mask -> bits (one warp per 32-j word, warp-strided)
    {
        const int wid_g = (blockIdx.x * 256 + threadIdx.x) >> 5;
        const int lane  = threadIdx.x & 31;
        const int nwarp = stride >> 5;
        for (int w = wid_g; w < NN * NWORD; w += nwarp) {
            int row = w >> 7;            // / NWORD
            int wd  = w & (NWORD - 1);
            int m = mask[(size_t)row * NN + wd * 32 + lane];
            uint32_t b = __ballot_sync(0xffffffffu, m > 0);
            if (lane == 0) g_bits[w] = b;
        }
    }
}

// ---------------------------------------------------------------------------
// Kernel A: Wh = h @ W + bW via fp16 HMMA hi/lo split; fused el/er and
// per-head er-max (CTA reduce + 1 atomicMax).
// ---------------------------------------------------------------------------
#define ASTRIDE 72
#define WH_SMEM (128 * ASTRIDE * 2 * 2 + 64 * ASTRIDE * 2 * 2)

__global__ void __launch_bounds__(256) wh_mma_kernel(
    const float* __restrict__ bW, const float* __restrict__ a_l,
    const float* __restrict__ a_r, const float* __restrict__ bA)
{
    extern __shared__ __align__(16) unsigned short sm[];
    unsigned short* Ah = sm;
    unsigned short* Al = Ah + 128 * ASTRIDE;
    unsigned short* Bh = Al + 128 * ASTRIDE;
    unsigned short* Bl = Bh + 64 * ASTRIDE;
    __shared__ float redmax[8];

    const int t    = threadIdx.x;
    const int warp = t >> 5;
    const int lane = t & 31;
    const int i0   = blockIdx.x * 128;
    const int hh   = blockIdx.y;

    const uint32_t ahB = smem_u32(Ah), alB = smem_u32(Al);
    const uint32_t bhB = smem_u32(Bh), blB = smem_u32(Bl);

    float acc[8][4];
#pragma unroll
    for (int n = 0; n < 8; n++)
#pragma unroll
        for (int j = 0; j < 4; j++) acc[n][j] = 0.f;

    const uint32_t aRow = (uint32_t)(16 * warp + (lane & 15)) * (ASTRIDE * 2) + ((lane & 16) ? 16 : 0);
    const uint32_t bRow = (uint32_t)(lane & 15) * (ASTRIDE * 2) + ((lane & 16) ? 16 : 0);

    for (int ch = 0; ch < FIN / 64; ch++) {
        const int kc = ch * 64;
        __syncthreads();
#pragma unroll
        for (int it = 0; it < 4; it++) {
            int id = t + 256 * it;
            int r = id >> 3, c = id & 7;
            size_t src = (size_t)(i0 + r) * FIN + kc + c * 8;
            *(uint4*)&Ah[r * ASTRIDE + c * 8] = *(const uint4*)(g_h16hi + src);
            *(uint4*)&Al[r * ASTRIDE + c * 8] = *(const uint4*)(g_h16lo + src);
        }
#pragma unroll
        for (int it = 0; it < 2; it++) {
            int id = t + 256 * it;
            int r = id >> 3, c = id & 7;
            size_t src = ((size_t)hh * FIN + kc + r) * FO + c * 8;
            *(uint4*)&Bh[r * ASTRIDE + c * 8] = *(const uint4*)(g_w16hi + src);
            *(uint4*)&Bl[r * ASTRIDE + c * 8] = *(const uint4*)(g_w16lo + src);
        }
        __syncthreads();

#pragma unroll
        for (int kt = 0; kt < 4; kt++) {
            uint32_t ah0, ah1, ah2, ah3, al0, al1, al2, al3;
            LDSM4(ah0, ah1, ah2, ah3, ahB + aRow + kt * 32);
            LDSM4(al0, al1, al2, al3, alB + aRow + kt * 32);
            const uint32_t kOff = (uint32_t)(16 * kt) * (ASTRIDE * 2) + bRow;
#pragma unroll
            for (int ntp = 0; ntp < 4; ntp++) {
                uint32_t bh0, bh1, bh2, bh3, bl0, bl1, bl2, bl3;
                LDSM4T(bh0, bh1, bh2, bh3, bhB + kOff + 32 * ntp);
                LDSM4T(bl0, bl1, bl2, bl3, blB + kOff + 32 * ntp);
                MMA16816F16(acc[2 * ntp],     ah0, ah1, ah2, ah3, bh0, bh1);
                MMA16816F16(acc[2 * ntp],     al0, al1, al2, al3, bh0, bh1);
                MMA16816F16(acc[2 * ntp],     ah0, ah1, ah2, ah3, bl0, bl1);
                MMA16816F16(acc[2 * ntp + 1], ah0, ah1, ah2, ah3, bh2, bh3);
                MMA16816F16(acc[2 * ntp + 1], al0, al1, al2, al3, bh2, bh3);
                MMA16816F16(acc[2 * ntp + 1], ah0, ah1, ah2, ah3, bl2, bl3);
            }
        }
    }

    // ---- epilogue: bias, store fp16 Wh, fused el/er, er-max ----
    const int q  = lane >> 2;
    const int c2 = 2 * (lane & 3);
    const int r0 = i0 + 16 * warp + q;
    const int r1 = r0 + 8;

    float dl0 = 0.f, dr0 = 0.f, dl1 = 0.f, dr1 = 0.f;
#pragma unroll
    for (int nt = 0; nt < 8; nt++) {
        int col = 8 * nt + c2;
        float2 bw = *(const float2*)(bW + hh * FO + col);
        float2 al = *(const float2*)(a_l + hh * FO + col);
        float2 ar = *(const float2*)(a_r + hh * FO + col);
        float v00 = acc[nt][0] + bw.x, v01 = acc[nt][1] + bw.y;
        float v10 = acc[nt][2] + bw.x, v11 = acc[nt][3] + bw.y;
        *(uint32_t*)(g_wh16 + ((size_t)hh * NN + r0) * FO + col) = pack_hi_f16x2(v00, v01);
        *(uint32_t*)(g_wh16 + ((size_t)hh * NN + r1) * FO + col) = pack_hi_f16x2(v10, v11);
        dl0 += v00 * al.x + v01 * al.y;
        dr0 += v00 * ar.x + v01 * ar.y;
        dl1 += v10 * al.x + v11 * al.y;
        dr1 += v10 * ar.x + v11 * ar.y;
    }
#pragma unroll
    for (int off = 1; off < 4; off <<= 1) {
        dl0 += __shfl_xor_sync(0xffffffffu, dl0, off);
        dr0 += __shfl_xor_sync(0xffffffffu, dr0, off);
        dl1 += __shfl_xor_sync(0xffffffffu, dl1, off);
        dr1 += __shfl_xor_sync(0xffffffffu, dr1, off);
    }
    float er0s = dr0 * LOG2E, er1s = dr1 * LOG2E;
    if ((lane & 3) == 0) {
        float ba = bA[hh];
        g_el[hh * NN + r0] = (dl0 + ba) * LOG2E;
        g_er[hh * NN + r0] = er0s;
        g_el[hh * NN + r1] = (dl1 + ba) * LOG2E;
        g_er[hh * NN + r1] = er1s;
    }
    // warp max of er over its 16 rows -> smem -> one atomic per CTA
    float wm = fmaxf(er0s, er1s);
#pragma unroll
    for (int off = 4; off < 32; off <<= 1)
        wm = fmaxf(wm, __shfl_xor_sync(0xffffffffu, wm, off));
    if (lane == 0) redmax[warp] = wm;
    __syncthreads();
    if (t == 0) {
        float m = redmax[0];
#pragma unroll
        for (int w = 1; w < 8; w++) m = fmaxf(m, redmax[w]);
        atomicMax(&g_ermax_enc[hh], f2ord(m));
    }
}

// ---------------------------------------------------------------------------
// Kernel C: fp16 HMMA flash-GAT. er staged in smem; bits prefetched; score
// phase software-pipelined one kt step ahead of its MMAs.
// ---------------------------------------------------------------------------
__device__ __forceinline__ float elu(float v) {
    return v > 0.f ? v : (__expf(v) - 1.f);
}

__device__ __forceinline__ uint32_t pscore2(float2 ed, float2 er, uint32_t b2) {
    float x0 = ed.x + er.x;
    float a0 = fmaxf(x0, fmaf(ALPHA, x0, ed.y));
    float x1 = ed.x + er.y;
    float a1 = fmaxf(x1, fmaf(ALPHA, x1, ed.y));
    uint32_t ph, pe;
    asm("cvt.rn.f16x2.f32 %0, %1, %2;" : "=r"(ph) : "f"(a1), "f"(a0));
    asm("ex2.approx.f16x2 %0, %1;" : "=r"(pe) : "r"(ph));
    uint32_t msk = ((b2 & 1u) ? 0x0000FFFFu : 0u) | ((b2 & 2u) ? 0xFFFF0000u : 0u);
    return pe & msk;
}

#define BSTRIDE 72

__global__ void __launch_bounds__(256, 2) gat_attn_mma_kernel(float* __restrict__ out)
{
    __shared__ __align__(16) unsigned short Bs[2][64 * BSTRIDE];
    __shared__ float2 els2[128];
    __shared__ __align__(16) float ers[NN];   // 16KB: the head's er row

    const int t    = threadIdx.x;
    const int warp = t >> 5;
    const int lane = t & 31;
    const int i0   = blockIdx.x * 128;
    const int hh   = blockIdx.y;

    // stage er into smem (coalesced float4)
    {
        const float4* src = (const float4*)(g_er + hh * NN);
#pragma unroll
        for (int it = 0; it < NN / 4 / 256; it++)
            ((float4*)ers)[t + 256 * it] = src[t + 256 * it];
    }

    if (t < 128) {
        float e = g_el[hh * NN + i0 + t];
        float z = e + ord2f(g_ermax_enc[hh]);
        float c = fmaxf(z, ALPHA * z);
        els2[t] = make_float2(e - c, (ALPHA - 1.f) * c);
    }

    const int q  = lane >> 2;
    const int c2 = 2 * (lane & 3);
    const int rw0 = 16 * warp + q;

    const unsigned short* gwh = g_wh16 + (size_t)hh * NN * FO;
    const uint32_t* bitrow = g_bits + (size_t)(i0 + 16 * warp + (lane >> 1)) * NWORD + (lane & 1);

    const uint32_t bBase = smem_u32(Bs);
    const uint32_t lrowOff = (uint32_t)(lane & 15) * (BSTRIDE * 2) + ((lane & 16) ? 16 : 0);

    const int lk0 = t >> 3, lc0 = t & 7;
    const int lk1 = (t + 256) >> 3, lc1 = t & 7;

    float acc[8][4];
#pragma unroll
    for (int n = 0; n < 8; n++)
#pragma unroll
        for (int j = 0; j < 4; j++) acc[n][j] = 0.f;
    float accd[4] = {0.f, 0.f, 0.f, 0.f};
    const uint32_t ONES = 0x3C003C00u;

    {
        uint4 va = *(const uint4*)(gwh + (size_t)lk0 * FO + lc0 * 8);
        uint4 vb = *(const uint4*)(gwh + (size_t)lk1 * FO + lc1 * 8);
        *(uint4*)&Bs[0][lk0 * BSTRIDE + lc0 * 8] = va;
        *(uint4*)&Bs[0][lk1 * BSTRIDE + lc1 * 8] = vb;
    }
    uint32_t bvNext = bitrow[0];   // bits for tile 0
    __syncthreads();

    const float2 ec0 = els2[rw0];
    const float2 ec1 = els2[rw0 + 8];

    // score block: jb0 = tile j-base; scores for step kt into a[4]
    auto scoreblk = [&](int jb0, int kt, uint32_t W00, uint32_t W01,
                        uint32_t W10, uint32_t W11, uint32_t* a) {
        const int jb = jb0 + 16 * kt + c2;
        float2 e0 = *(const float2*)(ers + jb);
        float2 e1 = *(const float2*)(ers + jb + 8);
        uint32_t wr0 = (kt < 2) ? W00 : W01;
        uint32_t wr1 = (kt < 2) ? W10 : W11;
        const int sb = (kt & 1) * 16;
        uint32_t v0 = wr0 >> (sb + c2);
        uint32_t v1 = wr1 >> (sb + c2);
        a[0] = pscore2(ec0, e0, v0 & 3u);
        a[1] = pscore2(ec1, e0, v1 & 3u);
        a[2] = pscore2(ec0, e1, (v0 >> 8) & 3u);
        a[3] = pscore2(ec1, e1, (v1 >> 8) & 3u);
    };

    // prologue: shfl w's + scores for tile 0, kt 0
    uint32_t w00, w01, w10, w11;
    {
        uint32_t bv = bvNext;
        w00 = __shfl_sync(0xffffffffu, bv, 2 * q);
        w01 = __shfl_sync(0xffffffffu, bv, 2 * q + 1);
        w10 = __shfl_sync(0xffffffffu, bv, 2 * q + 16);
        w11 = __shfl_sync(0xffffffffu, bv, 2 * q + 17);
    }
    uint32_t aF[4];
    scoreblk(0, 0, w00, w01, w10, w11, aF);

    for (int tile = 0; tile < NN / 64; tile++) {
        const int j0 = tile * 64;
        const int cur = tile & 1;
        const bool last = (tile == NN / 64 - 1);

        if (!last) bvNext = bitrow[(uint32_t)((j0 >> 5) + 2)];

        uint4 na, nb;
        if (!last) {
            const unsigned short* src = gwh + (size_t)(j0 + 64) * FO;
            na = *(const uint4*)(src + (size_t)lk0 * FO + lc0 * 8);
            nb = *(const uint4*)(src + (size_t)lk1 * FO + lc1 * 8);
        }

        const uint32_t bufOff = bBase + cur * (64 * BSTRIDE * 2) + lrowOff;

#pragma unroll
        for (int kt = 0; kt < 4; kt++) {
            uint32_t aN[4];
            if (kt < 3)
                scoreblk(j0, kt + 1, w00, w01, w10, w11, aN);

            const uint32_t kOff = bufOff + (uint32_t)(16 * kt) * (BSTRIDE * 2);
#pragma unroll
            for (int ntp = 0; ntp < 4; ntp++) {
                uint32_t b0, b1, b2, b3;
                LDSM4T(b0, b1, b2, b3, kOff + 32 * ntp);
                MMA16816F16(acc[2 * ntp],     aF[0], aF[1], aF[2], aF[3], b0, b1);
                MMA16816F16(acc[2 * ntp + 1], aF[0], aF[1], aF[2], aF[3], b2, b3);
            }
            MMA16816F16(accd, aF[0], aF[1], aF[2], aF[3], ONES, ONES);

            if (kt < 3) {
                aF[0] = aN[0]; aF[1] = aN[1]; aF[2] = aN[2]; aF[3] = aN[3];
            }
        }

        // next tile's shfl + kt0 scores (uses ers/regs only, not Bs)
        if (!last) {
            uint32_t bv = bvNext;
            w00 = __shfl_sync(0xffffffffu, bv, 2 * q);
            w01 = __shfl_sync(0xffffffffu, bv, 2 * q + 1);
            w10 = __shfl_sync(0xffffffffu, bv, 2 * q + 16);
            w11 = __shfl_sync(0xffffffffu, bv, 2 * q + 17);
            scoreblk(j0 + 64, 0, w00, w01, w10, w11, aF);

            unsigned short* dst = &Bs[cur ^ 1][0];
            *(uint4*)&dst[lk0 * BSTRIDE + lc0 * 8] = na;
            *(uint4*)&dst[lk1 * BSTRIDE + lc1 * 8] = nb;
        }
        __syncthreads();
    }

    const float inv0 = 1.f / accd[0];
    const float inv1 = 1.f / accd[2];

    float* ob0 = out + (size_t)(i0 + rw0) * OUTW + hh * FO + c2;
    float* ob1 = ob0 + (size_t)8 * OUTW;
#pragma unroll
    for (int nt = 0; nt < 8; nt++) {
        float2 v0 = make_float2(elu(acc[nt][0] * inv0), elu(acc[nt][1] * inv0));
        float2 v1 = make_float2(elu(acc[nt][2] * inv1), elu(acc[nt][3] * inv1));
        *(float2*)(ob0 + 8 * nt) = v0;
        *(float2*)(ob1 + 8 * nt) = v1;
    }
}

// ---------------------------------------------------------------------------
extern "C" void kernel_launch(void* const* d_in, const int* in_sizes, int n_in,
                              void* d_out, int out_size)
{
    const float* h    = (const float*)d_in[0];  // [N, FIN]
    const int*   mask = (const int*)  d_in[1];  // [N, N]
    const float* W    = (const float*)d_in[2];  // [H, FIN, FO]
    const float* bW   = (const float*)d_in[3];  // [H, FO]
    const float* a_l  = (const float*)d_in[4];  // [H, FO]
    const float* a_r  = (const float*)d_in[5];  // [H, FO]
    const float* bA   = (const float*)d_in[6];  // [H]
    float* out = (float*)d_out;                 // [N, H*FO]

    cudaFuncSetAttribute(wh_mma_kernel,
                         cudaFuncAttributeMaxDynamicSharedMemorySize, WH_SMEM);

    prep_kernel<<<1024, 256>>>(h, W, mask);
    wh_mma_kernel<<<dim3(NN / 128, NH), 256, WH_SMEM>>>(bW, a_l, a_r, bA);
    gat_attn_mma_kernel<<<dim3(NN / 128, NH), 256>>>(out);
}

// round 11
// speedup vs baseline: 1.8349x; 1.1470x over previous
#include <cuda_runtime.h>
#include <cuda_fp16.h>
#include <cstdint>

#define NN 4096
#define FIN 512
#define FO 64
#define NH 8
#define ALPHA 0.2f
#define OUTW (NH * FO)  /* 512 */
#define LOG2E 1.4426950408889634f
#define NWORD (NN / 32)  /* 128 */

// ---------------------------------------------------------------------------
// Scratch (static device globals)
// ---------------------------------------------------------------------------
__device__ unsigned short g_h16hi[NN * FIN];     // fp16 hi of h, [n][k]
__device__ unsigned short g_h16lo[NN * FIN];     // fp16 lo of h, [n][k]
__device__ unsigned short g_w16hi[NH * FIN * FO];// fp16 hi of W, [h][k][n]
__device__ unsigned short g_w16lo[NH * FIN * FO];
__device__ unsigned short g_wh16[NH * NN * FO];  // fp16 Wh, [h][n][o]
__device__ float g_el[NH * NN];                  // el * log2e (incl bA)
__device__ float g_er[NH * NN];                  // er * log2e
__device__ unsigned int g_ermax_enc[NH];         // order-preserving encoded max
__device__ uint32_t g_bits[NN * NWORD];          // mask bitmap [i][j/32]

__device__ __forceinline__ uint32_t smem_u32(const void* p) {
    uint32_t a;
    asm("{ .reg .u64 t; cvta.to.shared.u64 t, %1; cvt.u32.u64 %0, t; }" : "=r"(a) : "l"(p));
    return a;
}

// order-preserving float <-> uint encoding (for atomicMax on any-sign floats)
__device__ __forceinline__ unsigned int f2ord(float f) {
    unsigned int u = __float_as_uint(f);
    return (u & 0x80000000u) ? ~u : (u | 0x80000000u);
}
__device__ __forceinline__ float ord2f(unsigned int k) {
    unsigned int u = (k & 0x80000000u) ? (k & 0x7FFFFFFFu) : ~k;
    return __uint_as_float(u);
}

#define MMA16816F16(acc, a0, a1, a2, a3, b0, b1) \
    asm volatile("mma.sync.aligned.m16n8k16.row.col.f32.f16.f16.f32 " \
        "{%0,%1,%2,%3}, {%4,%5,%6,%7}, {%8,%9}, {%0,%1,%2,%3};" \
        : "+f"((acc)[0]), "+f"((acc)[1]), "+f"((acc)[2]), "+f"((acc)[3]) \
        : "r"(a0), "r"(a1), "r"(a2), "r"(a3), "r"(b0), "r"(b1))

#define LDSM4T(r0, r1, r2, r3, a) \
    asm volatile("ldmatrix.sync.aligned.m8n8.x4.trans.shared.b16 {%0,%1,%2,%3}, [%4];" \
        : "=r"(r0), "=r"(r1), "=r"(r2), "=r"(r3) : "r"(a))

#define LDSM4(r0, r1, r2, r3, a) \
    asm volatile("ldmatrix.sync.aligned.m8n8.x4.shared.b16 {%0,%1,%2,%3}, [%4];" \
        : "=r"(r0), "=r"(r1), "=r"(r2), "=r"(r3) : "r"(a))

__device__ __forceinline__ uint32_t pack_hi_f16x2(float a, float b) {
    uint32_t r;
    asm("cvt.rn.f16x2.f32 %0, %1, %2;" : "=r"(r) : "f"(b), "f"(a));
    return r;
}

// ---------------------------------------------------------------------------
// Kernel P: convert h and W to fp16 hi/lo; mask -> bitmap (MLP-4); init ermax.
// ---------------------------------------------------------------------------
__global__ void __launch_bounds__(256) prep_kernel(
    const float* __restrict__ h, const float* __restrict__ W,
    const int* __restrict__ mask)
{
    if (blockIdx.x == 0 && threadIdx.x < NH)
        g_ermax_enc[threadIdx.x] = 0u;  // below every encoded float

    const int stride = gridDim.x * 256;
    for (int i = blockIdx.x * 256 + threadIdx.x; i < NN * FIN / 4; i += stride) {
        float4 v = ((const float4*)h)[i];
        __half hx = __float2half_rn(v.x), hy = __float2half_rn(v.y);
        __half hz = __float2half_rn(v.z), hw = __float2half_rn(v.w);
        uint32_t hi0 = (uint32_t)__half_as_ushort(hx) | ((uint32_t)__half_as_ushort(hy) << 16);
        uint32_t hi1 = (uint32_t)__half_as_ushort(hz) | ((uint32_t)__half_as_ushort(hw) << 16);
        uint32_t lo0 = pack_hi_f16x2(v.x - __half2float(hx), v.y - __half2float(hy));
        uint32_t lo1 = pack_hi_f16x2(v.z - __half2float(hz), v.w - __half2float(hw));
        ((uint2*)g_h16hi)[i] = make_uint2(hi0, hi1);
        ((uint2*)g_h16lo)[i] = make_uint2(lo0, lo1);
    }
    for (int i = blockIdx.x * 256 + threadIdx.x; i < NH * FIN * FO / 4; i += stride) {
        float4 v = ((const float4*)W)[i];
        __half hx = __float2half_rn(v.x), hy = __float2half_rn(v.y);
        __half hz = __float2half_rn(v.z), hw = __float2half_rn(v.w);
        uint32_t hi0 = (uint32_t)__half_as_ushort(hx) | ((uint32_t)__half_as_ushort(hy) << 16);
        uint32_t hi1 = (uint32_t)__half_as_ushort(hz) | ((uint32_t)__half_as_ushort(hw) << 16);
        uint32_t lo0 = pack_hi_f16x2(v.x - __half2float(hx), v.y - __half2float(hy));
        uint32_t lo1 = pack_hi_f16x2(v.z - __half2float(hz), v.w - __half2float(hw));
        ((uint2*)g_w16hi)[i] = make_uint2(hi0, hi1);
        ((uint2*)g_w16lo)[i] = make_uint2(lo0, lo1);
    }
    // mask -> bits: each warp handles 4 consecutive bit-words per iteration
    // (4 independent LDGs over 512 contiguous bytes -> MLP=4), uint4 store.
    {
        const int wid_g = (blockIdx.x * 256 + threadIdx.x) >> 5;
        const int lane  = threadIdx.x & 31;
        const int nwarp = stride >> 5;
        for (int g = wid_g; g < NN * NWORD / 4; g += nwarp) {
            int w0  = 4 * g;
            int row = w0 >> 7;            // / NWORD
            int wd  = w0 & (NWORD - 1);
            const int* base = mask + (size_t)row * NN + wd * 32 + lane;
            int m0 = base[0];
            int m1 = base[32];
            int m2 = base[64];
            int m3 = base[96];
            uint32_t b0 = __ballot_sync(0xffffffffu, m0 > 0);
            uint32_t b1 = __ballot_sync(0xffffffffu, m1 > 0);
            uint32_t b2 = __ballot_sync(0xffffffffu, m2 > 0);
            uint32_t b3 = __ballot_sync(0xffffffffu, m3 > 0);
            if (lane == 0)
                *(uint4*)(g_bits + w0) = make_uint4(b0, b1, b2, b3);
        }
    }
}

// ---------------------------------------------------------------------------
// Kernel A: Wh = h @ W + bW via fp16 HMMA hi/lo split; fused el/er and
// per-head er-max (CTA reduce + 1 atomicMax).
// ---------------------------------------------------------------------------
#define ASTRIDE 72
#define WH_SMEM (128 * ASTRIDE * 2 * 2 + 64 * ASTRIDE * 2 * 2)

__global__ void __launch_bounds__(256) wh_mma_kernel(
    const float* __restrict__ bW, const float* __restrict__ a_l,
    const float* __restrict__ a_r, const float* __restrict__ bA)
{
    extern __shared__ __align__(16) unsigned short sm[];
    unsigned short* Ah = sm;
    unsigned short* Al = Ah + 128 * ASTRIDE;
    unsigned short* Bh = Al + 128 * ASTRIDE;
    unsigned short* Bl = Bh + 64 * ASTRIDE;
    __shared__ float redmax[8];

    const int t    = threadIdx.x;
    const int warp = t >> 5;
    const int lane = t & 31;
    const int i0   = blockIdx.x * 128;
    const int hh   = blockIdx.y;

    const uint32_t ahB = smem_u32(Ah), alB = smem_u32(Al);
    const uint32_t bhB = smem_u32(Bh), blB = smem_u32(Bl);

    float acc[8][4];
#pragma unroll
    for (int n = 0; n < 8; n++)
#pragma unroll
        for (int j = 0; j < 4; j++) acc[n][j] = 0.f;

    const uint32_t aRow = (uint32_t)(16 * warp + (lane & 15)) * (ASTRIDE * 2) + ((lane & 16) ? 16 : 0);
    const uint32_t bRow = (uint32_t)(lane & 15) * (ASTRIDE * 2) + ((lane & 16) ? 16 : 0);

    for (int ch = 0; ch < FIN / 64; ch++) {
        const int kc = ch * 64;
        __syncthreads();
#pragma unroll
        for (int it = 0; it < 4; it++) {
            int id = t + 256 * it;
            int r = id >> 3, c = id & 7;
            size_t src = (size_t)(i0 + r) * FIN + kc + c * 8;
            *(uint4*)&Ah[r * ASTRIDE + c * 8] = *(const uint4*)(g_h16hi + src);
            *(uint4*)&Al[r * ASTRIDE + c * 8] = *(const uint4*)(g_h16lo + src);
        }
#pragma unroll
        for (int it = 0; it < 2; it++) {
            int id = t + 256 * it;
            int r = id >> 3, c = id & 7;
            size_t src = ((size_t)hh * FIN + kc + r) * FO + c * 8;
            *(uint4*)&Bh[r * ASTRIDE + c * 8] = *(const uint4*)(g_w16hi + src);
            *(uint4*)&Bl[r * ASTRIDE + c * 8] = *(const uint4*)(g_w16lo + src);
        }
        __syncthreads();

#pragma unroll
        for (int kt = 0; kt < 4; kt++) {
            uint32_t ah0, ah1, ah2, ah3, al0, al1, al2, al3;
            LDSM4(ah0, ah1, ah2, ah3, ahB + aRow + kt * 32);
            LDSM4(al0, al1, al2, al3, alB + aRow + kt * 32);
            const uint32_t kOff = (uint32_t)(16 * kt) * (ASTRIDE * 2) + bRow;
#pragma unroll
            for (int ntp = 0; ntp < 4; ntp++) {
                uint32_t bh0, bh1, bh2, bh3, bl0, bl1, bl2, bl3;
                LDSM4T(bh0, bh1, bh2, bh3, bhB + kOff + 32 * ntp);
                LDSM4T(bl0, bl1, bl2, bl3, blB + kOff + 32 * ntp);
                MMA16816F16(acc[2 * ntp],     ah0, ah1, ah2, ah3, bh0, bh1);
                MMA16816F16(acc[2 * ntp],     al0, al1, al2, al3, bh0, bh1);
                MMA16816F16(acc[2 * ntp],     ah0, ah1, ah2, ah3, bl0, bl1);
                MMA16816F16(acc[2 * ntp + 1], ah0, ah1, ah2, ah3, bh2, bh3);
                MMA16816F16(acc[2 * ntp + 1], al0, al1, al2, al3, bh2, bh3);
                MMA16816F16(acc[2 * ntp + 1], ah0, ah1, ah2, ah3, bl2, bl3);
            }
        }
    }

    // ---- epilogue: bias, store fp16 Wh, fused el/er, er-max ----
    const int q  = lane >> 2;
    const int c2 = 2 * (lane & 3);
    const int r0 = i0 + 16 * warp + q;
    const int r1 = r0 + 8;

    float dl0 = 0.f, dr0 = 0.f, dl1 = 0.f, dr1 = 0.f;
#pragma unroll
    for (int nt = 0; nt < 8; nt++) {
        int col = 8 * nt + c2;
        float2 bw = *(const float2*)(bW + hh * FO + col);
        float2 al = *(const float2*)(a_l + hh * FO + col);
        float2 ar = *(const float2*)(a_r + hh * FO + col);
        float v00 = acc[nt][0] + bw.x, v01 = acc[nt][1] + bw.y;
        float v10 = acc[nt][2] + bw.x, v11 = acc[nt][3] + bw.y;
        *(uint32_t*)(g_wh16 + ((size_t)hh * NN + r0) * FO + col) = pack_hi_f16x2(v00, v01);
        *(uint32_t*)(g_wh16 + ((size_t)hh * NN + r1) * FO + col) = pack_hi_f16x2(v10, v11);
        dl0 += v00 * al.x + v01 * al.y;
        dr0 += v00 * ar.x + v01 * ar.y;
        dl1 += v10 * al.x + v11 * al.y;
        dr1 += v10 * ar.x + v11 * ar.y;
    }
#pragma unroll
    for (int off = 1; off < 4; off <<= 1) {
        dl0 += __shfl_xor_sync(0xffffffffu, dl0, off);
        dr0 += __shfl_xor_sync(0xffffffffu, dr0, off);
        dl1 += __shfl_xor_sync(0xffffffffu, dl1, off);
        dr1 += __shfl_xor_sync(0xffffffffu, dr1, off);
    }
    float er0s = dr0 * LOG2E, er1s = dr1 * LOG2E;
    if ((lane & 3) == 0) {
        float ba = bA[hh];
        g_el[hh * NN + r0] = (dl0 + ba) * LOG2E;
        g_er[hh * NN + r0] = er0s;
        g_el[hh * NN + r1] = (dl1 + ba) * LOG2E;
        g_er[hh * NN + r1] = er1s;
    }
    // warp max of er over its 16 rows -> smem -> one atomic per CTA
    float wm = fmaxf(er0s, er1s);
#pragma unroll
    for (int off = 4; off < 32; off <<= 1)
        wm = fmaxf(wm, __shfl_xor_sync(0xffffffffu, wm, off));
    if (lane == 0) redmax[warp] = wm;
    __syncthreads();
    if (t == 0) {
        float m = redmax[0];
#pragma unroll
        for (int w = 1; w < 8; w++) m = fmaxf(m, redmax[w]);
        atomicMax(&g_ermax_enc[hh], f2ord(m));
    }
}

// ---------------------------------------------------------------------------
// Kernel C: fp16 HMMA flash-GAT. er staged in smem; bits prefetched; score
// phase software-pipelined one kt step ahead of its MMAs.
// ---------------------------------------------------------------------------
__device__ __forceinline__ float elu(float v) {
    return v > 0.f ? v : (__expf(v) - 1.f);
}

__device__ __forceinline__ uint32_t pscore2(float2 ed, float2 er, uint32_t b2) {
    float x0 = ed.x + er.x;
    float a0 = fmaxf(x0, fmaf(ALPHA, x0, ed.y));
    float x1 = ed.x + er.y;
    float a1 = fmaxf(x1, fmaf(ALPHA, x1, ed.y));
    uint32_t ph, pe;
    asm("cvt.rn.f16x2.f32 %0, %1, %2;" : "=r"(ph) : "f"(a1), "f"(a0));
    asm("ex2.approx.f16x2 %0, %1;" : "=r"(pe) : "r"(ph));
    uint32_t msk = ((b2 & 1u) ? 0x0000FFFFu : 0u) | ((b2 & 2u) ? 0xFFFF0000u : 0u);
    return pe & msk;
}

#define BSTRIDE 72

__global__ void __launch_bounds__(256, 2) gat_attn_mma_kernel(float* __restrict__ out)
{
    __shared__ __align__(16) unsigned short Bs[2][64 * BSTRIDE];
    __shared__ float2 els2[128];
    __shared__ __align__(16) float ers[NN];   // 16KB: the head's er row

    const int t    = threadIdx.x;
    const int warp = t >> 5;
    const int lane = t & 31;
    const int i0   = blockIdx.x * 128;
    const int hh   = blockIdx.y;

    // stage er into smem (coalesced float4)
    {
        const float4* src = (const float4*)(g_er + hh * NN);
#pragma unroll
        for (int it = 0; it < NN / 4 / 256; it++)
            ((float4*)ers)[t + 256 * it] = src[t + 256 * it];
    }

    if (t < 128) {
        float e = g_el[hh * NN + i0 + t];
        float z = e + ord2f(g_ermax_enc[hh]);
        float c = fmaxf(z, ALPHA * z);
        els2[t] = make_float2(e - c, (ALPHA - 1.f) * c);
    }

    const int q  = lane >> 2;
    const int c2 = 2 * (lane & 3);
    const int rw0 = 16 * warp + q;

    const unsigned short* gwh = g_wh16 + (size_t)hh * NN * FO;
    const uint32_t* bitrow = g_bits + (size_t)(i0 + 16 * warp + (lane >> 1)) * NWORD + (lane & 1);

    const uint32_t bBase = smem_u32(Bs);
    const uint32_t lrowOff = (uint32_t)(lane & 15) * (BSTRIDE * 2) + ((lane & 16) ? 16 : 0);

    const int lk0 = t >> 3, lc0 = t & 7;
    const int lk1 = (t + 256) >> 3, lc1 = t & 7;

    float acc[8][4];
#pragma unroll
    for (int n = 0; n < 8; n++)
#pragma unroll
        for (int j = 0; j < 4; j++) acc[n][j] = 0.f;
    float accd[4] = {0.f, 0.f, 0.f, 0.f};
    const uint32_t ONES = 0x3C003C00u;

    {
        uint4 va = *(const uint4*)(gwh + (size_t)lk0 * FO + lc0 * 8);
        uint4 vb = *(const uint4*)(gwh + (size_t)lk1 * FO + lc1 * 8);
        *(uint4*)&Bs[0][lk0 * BSTRIDE + lc0 * 8] = va;
        *(uint4*)&Bs[0][lk1 * BSTRIDE + lc1 * 8] = vb;
    }
    uint32_t bvNext = bitrow[0];   // bits for tile 0
    __syncthreads();

    const float2 ec0 = els2[rw0];
    const float2 ec1 = els2[rw0 + 8];

    // score block: jb0 = tile j-base; scores for step kt into a[4]
    auto scoreblk = [&](int jb0, int kt, uint32_t W00, uint32_t W01,
                        uint32_t W10, uint32_t W11, uint32_t* a) {
        const int jb = jb0 + 16 * kt + c2;
        float2 e0 = *(const float2*)(ers + jb);
        float2 e1 = *(const float2*)(ers + jb + 8);
        uint32_t wr0 = (kt < 2) ? W00 : W01;
        uint32_t wr1 = (kt < 2) ? W10 : W11;
        const int sb = (kt & 1) * 16;
        uint32_t v0 = wr0 >> (sb + c2);
        uint32_t v1 = wr1 >> (sb + c2);
        a[0] = pscore2(ec0, e0, v0 & 3u);
        a[1] = pscore2(ec1, e0, v1 & 3u);
        a[2] = pscore2(ec0, e1, (v0 >> 8) & 3u);
        a[3] = pscore2(ec1, e1, (v1 >> 8) & 3u);
    };

    // prologue: shfl w's + scores for tile 0, kt 0
    uint32_t w00, w01, w10, w11;
    {
        uint32_t bv = bvNext;
        w00 = __shfl_sync(0xffffffffu, bv, 2 * q);
        w01 = __shfl_sync(0xffffffffu, bv, 2 * q + 1);
        w10 = __shfl_sync(0xffffffffu, bv, 2 * q + 16);
        w11 = __shfl_sync(0xffffffffu, bv, 2 * q + 17);
    }
    uint32_t aF[4];
    scoreblk(0, 0, w00, w01, w10, w11, aF);

    for (int tile = 0; tile < NN / 64; tile++) {
        const int j0 = tile * 64;
        const int cur = tile & 1;
        const bool last = (tile == NN / 64 - 1);

        if (!last) bvNext = bitrow[(uint32_t)((j0 >> 5) + 2)];

        uint4 na, nb;
        if (!last) {
            const unsigned short* src = gwh + (size_t)(j0 + 64) * FO;
            na = *(const uint4*)(src + (size_t)lk0 * FO + lc0 * 8);
            nb = *(const uint4*)(src + (size_t)lk1 * FO + lc1 * 8);
        }

        const uint32_t bufOff = bBase + cur * (64 * BSTRIDE * 2) + lrowOff;

#pragma unroll
        for (int kt = 0; kt < 4; kt++) {
            uint32_t aN[4];
            if (kt < 3)
                scoreblk(j0, kt + 1, w00, w01, w10, w11, aN);

            const uint32_t kOff = bufOff + (uint32_t)(16 * kt) * (BSTRIDE * 2);
#pragma unroll
            for (int ntp = 0; ntp < 4; ntp++) {
                uint32_t b0, b1, b2, b3;
                LDSM4T(b0, b1, b2, b3, kOff + 32 * ntp);
                MMA16816F16(acc[2 * ntp],     aF[0], aF[1], aF[2], aF[3], b0, b1);
                MMA16816F16(acc[2 * ntp + 1], aF[0], aF[1], aF[2], aF[3], b2, b3);
            }
            MMA16816F16(accd, aF[0], aF[1], aF[2], aF[3], ONES, ONES);

            if (kt < 3) {
                aF[0] = aN[0]; aF[1] = aN[1]; aF[2] = aN[2]; aF[3] = aN[3];
            }
        }

        // next tile's shfl + kt0 scores (uses ers/regs only, not Bs)
        if (!last) {
            uint32_t bv = bvNext;
            w00 = __shfl_sync(0xffffffffu, bv, 2 * q);
            w01 = __shfl_sync(0xffffffffu, bv, 2 * q + 1);
            w10 = __shfl_sync(0xffffffffu, bv, 2 * q + 16);
            w11 = __shfl_sync(0xffffffffu, bv, 2 * q + 17);
            scoreblk(j0 + 64, 0, w00, w01, w10, w11, aF);

            unsigned short* dst = &Bs[cur ^ 1][0];
            *(uint4*)&dst[lk0 * BSTRIDE + lc0 * 8] = na;
            *(uint4*)&dst[lk1 * BSTRIDE + lc1 * 8] = nb;
        }
        __syncthreads();
    }

    const float inv0 = 1.f / accd[0];
    const float inv1 = 1.f / accd[2];

    float* ob0 = out + (size_t)(i0 + rw0) * OUTW + hh * FO + c2;
    float* ob1 = ob0 + (size_t)8 * OUTW;
#pragma unroll
    for (int nt = 0; nt < 8; nt++) {
        float2 v0 = make_float2(elu(acc[nt][0] * inv0), elu(acc[nt][1] * inv0));
        float2 v1 = make_float2(elu(acc[nt][2] * inv1), elu(acc[nt][3] * inv1));
        *(float2*)(ob0 + 8 * nt) = v0;
        *(float2*)(ob1 + 8 * nt) = v1;
    }
}

// ---------------------------------------------------------------------------
extern "C" void kernel_launch(void* const* d_in, const int* in_sizes, int n_in,
                              void* d_out, int out_size)
{
    const float* h    = (const float*)d_in[0];  // [N, FIN]
    const int*   mask = (const int*)  d_in[1];  // [N, N]
    const float* W    = (const float*)d_in[2];  // [H, FIN, FO]
    const float* bW   = (const float*)d_in[3];  // [H, FO]
    const float* a_l  = (const float*)d_in[4];  // [H, FO]
    const float* a_r  = (const float*)d_in[5];  // [H, FO]
    const float* bA   = (const float*)d_in[6];  // [H]
    float* out = (float*)d_out;                 // [N, H*FO]

    cudaFuncSetAttribute(wh_mma_kernel,
                         cudaFuncAttributeMaxDynamicSharedMemorySize, WH_SMEM);

    prep_kernel<<<1024, 256>>>(h, W, mask);
    wh_mma_kernel<<<dim3(NN / 128, NH), 256, WH_SMEM>>>(bW, a_l, a_r, bA);
    gat_attn_mma_kernel<<<dim3(NN / 128, NH), 256>>>(out);
}

// round 12
// speedup vs baseline: 1.8746x; 1.0216x over previous
#include <cuda_runtime.h>
#include <cuda_fp16.h>
#include <cstdint>

#define NN 4096
#define FIN 512
#define FO 64
#define NH 8
#define ALPHA 0.2f
#define OUTW (NH * FO)  /* 512 */
#define LOG2E 1.4426950408889634f
#define NWORD (NN / 32)  /* 128 */

// ---------------------------------------------------------------------------
// Scratch (static device globals)
// ---------------------------------------------------------------------------
__device__ unsigned short g_h16hi[NN * FIN];     // fp16 hi of h, [n][k]
__device__ unsigned short g_h16lo[NN * FIN];     // fp16 lo of h, [n][k]
__device__ unsigned short g_w16hi[NH * FIN * FO];// fp16 hi of W, [h][k][n]
__device__ unsigned short g_w16lo[NH * FIN * FO];
__device__ unsigned short g_wh16[NH * NN * FO];  // fp16 Wh, [h][n][o]
__device__ float g_el[NH * NN];                  // el * log2e (incl bA)
__device__ float g_er[NH * NN];                  // er * log2e
__device__ unsigned int g_ermax_enc[NH];         // order-preserving encoded max
__device__ uint32_t g_bits[NN * NWORD];          // mask bitmap [i][j/32]

__device__ __forceinline__ uint32_t smem_u32(const void* p) {
    uint32_t a;
    asm("{ .reg .u64 t; cvta.to.shared.u64 t, %1; cvt.u32.u64 %0, t; }" : "=r"(a) : "l"(p));
    return a;
}

__device__ __forceinline__ unsigned int f2ord(float f) {
    unsigned int u = __float_as_uint(f);
    return (u & 0x80000000u) ? ~u : (u | 0x80000000u);
}
__device__ __forceinline__ float ord2f(unsigned int k) {
    unsigned int u = (k & 0x80000000u) ? (k & 0x7FFFFFFFu) : ~k;
    return __uint_as_float(u);
}

#define MMA16816F16(acc, a0, a1, a2, a3, b0, b1) \
    asm volatile("mma.sync.aligned.m16n8k16.row.col.f32.f16.f16.f32 " \
        "{%0,%1,%2,%3}, {%4,%5,%6,%7}, {%8,%9}, {%0,%1,%2,%3};" \
        : "+f"((acc)[0]), "+f"((acc)[1]), "+f"((acc)[2]), "+f"((acc)[3]) \
        : "r"(a0), "r"(a1), "r"(a2), "r"(a3), "r"(b0), "r"(b1))

#define LDSM4T(r0, r1, r2, r3, a) \
    asm volatile("ldmatrix.sync.aligned.m8n8.x4.trans.shared.b16 {%0,%1,%2,%3}, [%4];" \
        : "=r"(r0), "=r"(r1), "=r"(r2), "=r"(r3) : "r"(a))

#define LDSM4(r0, r1, r2, r3, a) \
    asm volatile("ldmatrix.sync.aligned.m8n8.x4.shared.b16 {%0,%1,%2,%3}, [%4];" \
        : "=r"(r0), "=r"(r1), "=r"(r2), "=r"(r3) : "r"(a))

__device__ __forceinline__ uint32_t pack_hi_f16x2(float a, float b) {
    uint32_t r;
    asm("cvt.rn.f16x2.f32 %0, %1, %2;" : "=r"(r) : "f"(b), "f"(a));
    return r;
}

// ---------------------------------------------------------------------------
// Kernel P: convert h and W to fp16 hi/lo; mask -> bitmap (MLP-16); init ermax.
// ---------------------------------------------------------------------------
__global__ void __launch_bounds__(256) prep_kernel(
    const float* __restrict__ h, const float* __restrict__ W,
    const int* __restrict__ mask)
{
    if (blockIdx.x == 0 && threadIdx.x < NH)
        g_ermax_enc[threadIdx.x] = 0u;  // below every encoded float

    const int stride = gridDim.x * 256;
    for (int i = blockIdx.x * 256 + threadIdx.x; i < NN * FIN / 4; i += stride) {
        float4 v = ((const float4*)h)[i];
        __half hx = __float2half_rn(v.x), hy = __float2half_rn(v.y);
        __half hz = __float2half_rn(v.z), hw = __float2half_rn(v.w);
        uint32_t hi0 = (uint32_t)__half_as_ushort(hx) | ((uint32_t)__half_as_ushort(hy) << 16);
        uint32_t hi1 = (uint32_t)__half_as_ushort(hz) | ((uint32_t)__half_as_ushort(hw) << 16);
        uint32_t lo0 = pack_hi_f16x2(v.x - __half2float(hx), v.y - __half2float(hy));
        uint32_t lo1 = pack_hi_f16x2(v.z - __half2float(hz), v.w - __half2float(hw));
        ((uint2*)g_h16hi)[i] = make_uint2(hi0, hi1);
        ((uint2*)g_h16lo)[i] = make_uint2(lo0, lo1);
    }
    for (int i = blockIdx.x * 256 + threadIdx.x; i < NH * FIN * FO / 4; i += stride) {
        float4 v = ((const float4*)W)[i];
        __half hx = __float2half_rn(v.x), hy = __float2half_rn(v.y);
        __half hz = __float2half_rn(v.z), hw = __float2half_rn(v.w);
        uint32_t hi0 = (uint32_t)__half_as_ushort(hx) | ((uint32_t)__half_as_ushort(hy) << 16);
        uint32_t hi1 = (uint32_t)__half_as_ushort(hz) | ((uint32_t)__half_as_ushort(hw) << 16);
        uint32_t lo0 = pack_hi_f16x2(v.x - __half2float(hx), v.y - __half2float(hy));
        uint32_t lo1 = pack_hi_f16x2(v.z - __half2float(hz), v.w - __half2float(hw));
        ((uint2*)g_w16hi)[i] = make_uint2(hi0, hi1);
        ((uint2*)g_w16lo)[i] = make_uint2(lo0, lo1);
    }
    // mask -> bits: each warp handles 16 consecutive bit-words per iteration
    // (16 independent LDGs over 2KB contiguous -> MLP=16), 4 uint4 stores.
    {
        const int wid_g = (blockIdx.x * 256 + threadIdx.x) >> 5;
        const int lane  = threadIdx.x & 31;
        const int nwarp = stride >> 5;
        for (int g = wid_g; g < NN * NWORD / 16; g += nwarp) {
            int w0  = 16 * g;
            int row = w0 >> 7;            // / NWORD
            int wd  = w0 & (NWORD - 1);   // multiple of 16, stays in row
            const int* base = mask + (size_t)row * NN + wd * 32 + lane;
            int m[16];
#pragma unroll
            for (int k = 0; k < 16; k++) m[k] = base[32 * k];
            uint32_t b[16];
#pragma unroll
            for (int k = 0; k < 16; k++) b[k] = __ballot_sync(0xffffffffu, m[k] > 0);
            if (lane == 0) {
#pragma unroll
                for (int s = 0; s < 4; s++)
                    *(uint4*)(g_bits + w0 + 4 * s) =
                        make_uint4(b[4 * s], b[4 * s + 1], b[4 * s + 2], b[4 * s + 3]);
            }
        }
    }
}

// ---------------------------------------------------------------------------
// Kernel A: Wh = h @ W + bW via fp16 HMMA hi/lo split; fused el/er and
// per-head er-max (CTA reduce + 1 atomicMax).
// ---------------------------------------------------------------------------
#define ASTRIDE 72
#define WH_SMEM (128 * ASTRIDE * 2 * 2 + 64 * ASTRIDE * 2 * 2)

__global__ void __launch_bounds__(256) wh_mma_kernel(
    const float* __restrict__ bW, const float* __restrict__ a_l,
    const float* __restrict__ a_r, const float* __restrict__ bA)
{
    extern __shared__ __align__(16) unsigned short sm[];
    unsigned short* Ah = sm;
    unsigned short* Al = Ah + 128 * ASTRIDE;
    unsigned short* Bh = Al + 128 * ASTRIDE;
    unsigned short* Bl = Bh + 64 * ASTRIDE;
    __shared__ float redmax[8];

    const int t    = threadIdx.x;
    const int warp = t >> 5;
    const int lane = t & 31;
    const int i0   = blockIdx.x * 128;
    const int hh   = blockIdx.y;

    const uint32_t ahB = smem_u32(Ah), alB = smem_u32(Al);
    const uint32_t bhB = smem_u32(Bh), blB = smem_u32(Bl);

    float acc[8][4];
#pragma unroll
    for (int n = 0; n < 8; n++)
#pragma unroll
        for (int j = 0; j < 4; j++) acc[n][j] = 0.f;

    const uint32_t aRow = (uint32_t)(16 * warp + (lane & 15)) * (ASTRIDE * 2) + ((lane & 16) ? 16 : 0);
    const uint32_t bRow = (uint32_t)(lane & 15) * (ASTRIDE * 2) + ((lane & 16) ? 16 : 0);

    for (int ch = 0; ch < FIN / 64; ch++) {
        const int kc = ch * 64;
        __syncthreads();
#pragma unroll
        for (int it = 0; it < 4; it++) {
            int id = t + 256 * it;
            int r = id >> 3, c = id & 7;
            size_t src = (size_t)(i0 + r) * FIN + kc + c * 8;
            *(uint4*)&Ah[r * ASTRIDE + c * 8] = *(const uint4*)(g_h16hi + src);
            *(uint4*)&Al[r * ASTRIDE + c * 8] = *(const uint4*)(g_h16lo + src);
        }
#pragma unroll
        for (int it = 0; it < 2; it++) {
            int id = t + 256 * it;
            int r = id >> 3, c = id & 7;
            size_t src = ((size_t)hh * FIN + kc + r) * FO + c * 8;
            *(uint4*)&Bh[r * ASTRIDE + c * 8] = *(const uint4*)(g_w16hi + src);
            *(uint4*)&Bl[r * ASTRIDE + c * 8] = *(const uint4*)(g_w16lo + src);
        }
        __syncthreads();

#pragma unroll
        for (int kt = 0; kt < 4; kt++) {
            uint32_t ah0, ah1, ah2, ah3, al0, al1, al2, al3;
            LDSM4(ah0, ah1, ah2, ah3, ahB + aRow + kt * 32);
            LDSM4(al0, al1, al2, al3, alB + aRow + kt * 32);
            const uint32_t kOff = (uint32_t)(16 * kt) * (ASTRIDE * 2) + bRow;
#pragma unroll
            for (int ntp = 0; ntp < 4; ntp++) {
                uint32_t bh0, bh1, bh2, bh3, bl0, bl1, bl2, bl3;
                LDSM4T(bh0, bh1, bh2, bh3, bhB + kOff + 32 * ntp);
                LDSM4T(bl0, bl1, bl2, bl3, blB + kOff + 32 * ntp);
                MMA16816F16(acc[2 * ntp],     ah0, ah1, ah2, ah3, bh0, bh1);
                MMA16816F16(acc[2 * ntp],     al0, al1, al2, al3, bh0, bh1);
                MMA16816F16(acc[2 * ntp],     ah0, ah1, ah2, ah3, bl0, bl1);
                MMA16816F16(acc[2 * ntp + 1], ah0, ah1, ah2, ah3, bh2, bh3);
                MMA16816F16(acc[2 * ntp + 1], al0, al1, al2, al3, bh2, bh3);
                MMA16816F16(acc[2 * ntp + 1], ah0, ah1, ah2, ah3, bl2, bl3);
            }
        }
    }

    // ---- epilogue: bias, store fp16 Wh, fused el/er, er-max ----
    const int q  = lane >> 2;
    const int c2 = 2 * (lane & 3);
    const int r0 = i0 + 16 * warp + q;
    const int r1 = r0 + 8;

    float dl0 = 0.f, dr0 = 0.f, dl1 = 0.f, dr1 = 0.f;
#pragma unroll
    for (int nt = 0; nt < 8; nt++) {
        int col = 8 * nt + c2;
        float2 bw = *(const float2*)(bW + hh * FO + col);
        float2 al = *(const float2*)(a_l + hh * FO + col);
        float2 ar = *(const float2*)(a_r + hh * FO + col);
        float v00 = acc[nt][0] + bw.x, v01 = acc[nt][1] + bw.y;
        float v10 = acc[nt][2] + bw.x, v11 = acc[nt][3] + bw.y;
        *(uint32_t*)(g_wh16 + ((size_t)hh * NN + r0) * FO + col) = pack_hi_f16x2(v00, v01);
        *(uint32_t*)(g_wh16 + ((size_t)hh * NN + r1) * FO + col) = pack_hi_f16x2(v10, v11);
        dl0 += v00 * al.x + v01 * al.y;
        dr0 += v00 * ar.x + v01 * ar.y;
        dl1 += v10 * al.x + v11 * al.y;
        dr1 += v10 * ar.x + v11 * ar.y;
    }
#pragma unroll
    for (int off = 1; off < 4; off <<= 1) {
        dl0 += __shfl_xor_sync(0xffffffffu, dl0, off);
        dr0 += __shfl_xor_sync(0xffffffffu, dr0, off);
        dl1 += __shfl_xor_sync(0xffffffffu, dl1, off);
        dr1 += __shfl_xor_sync(0xffffffffu, dr1, off);
    }
    float er0s = dr0 * LOG2E, er1s = dr1 * LOG2E;
    if ((lane & 3) == 0) {
        float ba = bA[hh];
        g_el[hh * NN + r0] = (dl0 + ba) * LOG2E;
        g_er[hh * NN + r0] = er0s;
        g_el[hh * NN + r1] = (dl1 + ba) * LOG2E;
        g_er[hh * NN + r1] = er1s;
    }
    float wm = fmaxf(er0s, er1s);
#pragma unroll
    for (int off = 4; off < 32; off <<= 1)
        wm = fmaxf(wm, __shfl_xor_sync(0xffffffffu, wm, off));
    if (lane == 0) redmax[warp] = wm;
    __syncthreads();
    if (t == 0) {
        float m = redmax[0];
#pragma unroll
        for (int w = 1; w < 8; w++) m = fmaxf(m, redmax[w]);
        atomicMax(&g_ermax_enc[hh], f2ord(m));
    }
}

// ---------------------------------------------------------------------------
// Kernel C: fp16 HMMA flash-GAT, 128-wide j tiles (32 tiles, 8 kt each).
// er staged in smem; bits prefetched; score phase SW-pipelined one kt ahead;
// next-tile B prefetched in two register-reusing halves.
// ---------------------------------------------------------------------------
__device__ __forceinline__ float elu(float v) {
    return v > 0.f ? v : (__expf(v) - 1.f);
}

__device__ __forceinline__ uint32_t pscore2(float2 ed, float2 er, uint32_t b2) {
    float x0 = ed.x + er.x;
    float a0 = fmaxf(x0, fmaf(ALPHA, x0, ed.y));
    float x1 = ed.x + er.y;
    float a1 = fmaxf(x1, fmaf(ALPHA, x1, ed.y));
    uint32_t ph, pe;
    asm("cvt.rn.f16x2.f32 %0, %1, %2;" : "=r"(ph) : "f"(a1), "f"(a0));
    asm("ex2.approx.f16x2 %0, %1;" : "=r"(pe) : "r"(ph));
    uint32_t msk = ((b2 & 1u) ? 0x0000FFFFu : 0u) | ((b2 & 2u) ? 0xFFFF0000u : 0u);
    return pe & msk;
}

#define BSTRIDE 72
#define JT 128
#define ATTN_BS_BYTES (2 * JT * BSTRIDE * 2)            /* 36864 */
#define ATTN_SMEM (ATTN_BS_BYTES + 1024 + NN * 4)       /* + els2 + ers = 54272 */

__global__ void __launch_bounds__(256, 2) gat_attn_mma_kernel(float* __restrict__ out)
{
    extern __shared__ __align__(16) char dsm[];
    unsigned short* Bs = (unsigned short*)dsm;          // 2 x JT x BSTRIDE
    float2* els2 = (float2*)(dsm + ATTN_BS_BYTES);      // 128
    float* ers = (float*)(dsm + ATTN_BS_BYTES + 1024);  // NN

    const int t    = threadIdx.x;
    const int warp = t >> 5;
    const int lane = t & 31;
    const int i0   = blockIdx.x * 128;
    const int hh   = blockIdx.y;

    {
        const float4* src = (const float4*)(g_er + hh * NN);
#pragma unroll
        for (int it = 0; it < NN / 4 / 256; it++)
            ((float4*)ers)[t + 256 * it] = src[t + 256 * it];
    }

    if (t < 128) {
        float e = g_el[hh * NN + i0 + t];
        float z = e + ord2f(g_ermax_enc[hh]);
        float c = fmaxf(z, ALPHA * z);
        els2[t] = make_float2(e - c, (ALPHA - 1.f) * c);
    }

    const int q  = lane >> 2;
    const int c2 = 2 * (lane & 3);
    const int rw0 = 16 * warp + q;

    const unsigned short* gwh = g_wh16 + (size_t)hh * NN * FO;
    // lane loads uint2 = words {0,1} or {2,3} of its row's 4-word tile group
    const uint32_t* bitbase =
        g_bits + (size_t)(i0 + 16 * warp + (lane >> 1)) * NWORD + (lane & 1) * 2;

    const uint32_t bBase = smem_u32(Bs);
    const uint32_t lrowOff = (uint32_t)(lane & 15) * (BSTRIDE * 2) + ((lane & 16) ? 16 : 0);

    const int lk0 = t >> 3, lc0 = t & 7;          // rows 0..31 / 32..63 pattern
    const int lk1 = (t + 256) >> 3, lc1 = t & 7;

    float acc[8][4];
#pragma unroll
    for (int n = 0; n < 8; n++)
#pragma unroll
        for (int j = 0; j < 4; j++) acc[n][j] = 0.f;
    float accd[4] = {0.f, 0.f, 0.f, 0.f};
    const uint32_t ONES = 0x3C003C00u;

    // preload tile 0 (JT rows = two halves)
    {
#pragma unroll
        for (int hf = 0; hf < 2; hf++) {
            uint4 va = *(const uint4*)(gwh + (size_t)(hf * 64 + lk0) * FO + lc0 * 8);
            uint4 vb = *(const uint4*)(gwh + (size_t)(hf * 64 + lk1) * FO + lc1 * 8);
            *(uint4*)&Bs[(hf * 64 + lk0) * BSTRIDE + lc0 * 8] = va;
            *(uint4*)&Bs[(hf * 64 + lk1) * BSTRIDE + lc1 * 8] = vb;
        }
    }
    uint2 bvNext = *(const uint2*)(bitbase);   // bits for tile 0
    __syncthreads();

    const float2 ec0 = els2[rw0];
    const float2 ec1 = els2[rw0 + 8];

    uint32_t w0[4], w1[4];  // 4 bit-words per row-group per tile
    auto distrib = [&](uint2 bv) {
        w0[0] = __shfl_sync(0xffffffffu, bv.x, 2 * q);
        w0[1] = __shfl_sync(0xffffffffu, bv.y, 2 * q);
        w0[2] = __shfl_sync(0xffffffffu, bv.x, 2 * q + 1);
        w0[3] = __shfl_sync(0xffffffffu, bv.y, 2 * q + 1);
        w1[0] = __shfl_sync(0xffffffffu, bv.x, 2 * q + 16);
        w1[1] = __shfl_sync(0xffffffffu, bv.y, 2 * q + 16);
        w1[2] = __shfl_sync(0xffffffffu, bv.x, 2 * q + 17);
        w1[3] = __shfl_sync(0xffffffffu, bv.y, 2 * q + 17);
    };

    auto scoreblk = [&](int jb0, int kt, uint32_t* a) {
        const int jb = jb0 + 16 * kt + c2;
        float2 e0 = *(const float2*)(ers + jb);
        float2 e1 = *(const float2*)(ers + jb + 8);
        const int wi = kt >> 1;
        const int sb = (kt & 1) * 16;
        uint32_t v0 = w0[wi] >> (sb + c2);
        uint32_t v1 = w1[wi] >> (sb + c2);
        a[0] = pscore2(ec0, e0, v0 & 3u);
        a[1] = pscore2(ec1, e0, v1 & 3u);
        a[2] = pscore2(ec0, e1, (v0 >> 8) & 3u);
        a[3] = pscore2(ec1, e1, (v1 >> 8) & 3u);
    };

    distrib(bvNext);
    uint32_t aF[4];
    scoreblk(0, 0, aF);

    for (int tile = 0; tile < NN / JT; tile++) {
        const int j0 = tile * JT;
        const int cur = tile & 1;
        const bool last = (tile == NN / JT - 1);

        if (!last) bvNext = *(const uint2*)(bitbase + (tile + 1) * 4);

        uint4 na, nb;
        if (!last) {   // first half of next tile
            const unsigned short* src = gwh + (size_t)(j0 + JT) * FO;
            na = *(const uint4*)(src + (size_t)lk0 * FO + lc0 * 8);
            nb = *(const uint4*)(src + (size_t)lk1 * FO + lc1 * 8);
        }

        const uint32_t bufOff = bBase + cur * (JT * BSTRIDE * 2) + lrowOff;
        unsigned short* dst = &Bs[(cur ^ 1) * JT * BSTRIDE];

#pragma unroll
        for (int kt = 0; kt < 8; kt++) {
            uint32_t aN[4];
            if (kt < 7)
                scoreblk(j0, kt + 1, aN);

            const uint32_t kOff = bufOff + (uint32_t)(16 * kt) * (BSTRIDE * 2);
#pragma unroll
            for (int ntp = 0; ntp < 4; ntp++) {
                uint32_t b0, b1, b2, b3;
                LDSM4T(b0, b1, b2, b3, kOff + 32 * ntp);
                MMA16816F16(acc[2 * ntp],     aF[0], aF[1], aF[2], aF[3], b0, b1);
                MMA16816F16(acc[2 * ntp + 1], aF[0], aF[1], aF[2], aF[3], b2, b3);
            }
            MMA16816F16(accd, aF[0], aF[1], aF[2], aF[3], ONES, ONES);

            if (kt == 3 && !last) {   // store half 1, reuse regs for half 2
                *(uint4*)&dst[lk0 * BSTRIDE + lc0 * 8] = na;
                *(uint4*)&dst[lk1 * BSTRIDE + lc1 * 8] = nb;
                const unsigned short* src = gwh + (size_t)(j0 + JT + 64) * FO;
                na = *(const uint4*)(src + (size_t)lk0 * FO + lc0 * 8);
                nb = *(const uint4*)(src + (size_t)lk1 * FO + lc1 * 8);
            }

            if (kt < 7) {
                aF[0] = aN[0]; aF[1] = aN[1]; aF[2] = aN[2]; aF[3] = aN[3];
            }
        }

        if (!last) {
            *(uint4*)&dst[(64 + lk0) * BSTRIDE + lc0 * 8] = na;
            *(uint4*)&dst[(64 + lk1) * BSTRIDE + lc1 * 8] = nb;
            distrib(bvNext);
            scoreblk(j0 + JT, 0, aF);
        }
        __syncthreads();
    }

    const float inv0 = 1.f / accd[0];
    const float inv1 = 1.f / accd[2];

    float* ob0 = out + (size_t)(i0 + rw0) * OUTW + hh * FO + c2;
    float* ob1 = ob0 + (size_t)8 * OUTW;
#pragma unroll
    for (int nt = 0; nt < 8; nt++) {
        float2 v0 = make_float2(elu(acc[nt][0] * inv0), elu(acc[nt][1] * inv0));
        float2 v1 = make_float2(elu(acc[nt][2] * inv1), elu(acc[nt][3] * inv1));
        *(float2*)(ob0 + 8 * nt) = v0;
        *(float2*)(ob1 + 8 * nt) = v1;
    }
}

// ---------------------------------------------------------------------------
extern "C" void kernel_launch(void* const* d_in, const int* in_sizes, int n_in,
                              void* d_out, int out_size)
{
    const float* h    = (const float*)d_in[0];  // [N, FIN]
    const int*   mask = (const int*)  d_in[1];  // [N, N]
    const float* W    = (const float*)d_in[2];  // [H, FIN, FO]
    const float* bW   = (const float*)d_in[3];  // [H, FO]
    const float* a_l  = (const float*)d_in[4];  // [H, FO]
    const float* a_r  = (const float*)d_in[5];  // [H, FO]
    const float* bA   = (const float*)d_in[6];  // [H]
    float* out = (float*)d_out;                 // [N, H*FO]

    cudaFuncSetAttribute(wh_mma_kernel,
                         cudaFuncAttributeMaxDynamicSharedMemorySize, WH_SMEM);
    cudaFuncSetAttribute(gat_attn_mma_kernel,
                         cudaFuncAttributeMaxDynamicSharedMemorySize, ATTN_SMEM);

    prep_kernel<<<1024, 256>>>(h, W, mask);
    wh_mma_kernel<<<dim3(NN / 128, NH), 256, WH_SMEM>>>(bW, a_l, a_r, bA);
    gat_attn_mma_kernel<<<dim3(NN / 128, NH), 256, ATTN_SMEM>>>(out);
}

// round 13
// speedup vs baseline: 1.8771x; 1.0013x over previous
#include <cuda_runtime.h>
#include <cuda_fp16.h>
#include <cstdint>

#define NN 4096
#define FIN 512
#define FO 64
#define NH 8
#define ALPHA 0.2f
#define OUTW (NH * FO)  /* 512 */
#define LOG2E 1.4426950408889634f
#define NWORD (NN / 32)  /* 128 */

// ---------------------------------------------------------------------------
// Scratch (static device globals)
// ---------------------------------------------------------------------------
__device__ unsigned short g_h16hi[NN * FIN];     // fp16 hi of h, [n][k]
__device__ unsigned short g_h16lo[NN * FIN];     // fp16 lo of h, [n][k]
__device__ unsigned short g_w16hi[NH * FIN * FO];// fp16 hi of W, [h][k][n]
__device__ unsigned short g_w16lo[NH * FIN * FO];
__device__ unsigned short g_wh16[NH * NN * FO];  // fp16 Wh, [h][n][o]
__device__ float g_el[NH * NN];                  // el * log2e (incl bA)
__device__ float g_er[NH * NN];                  // er * log2e
__device__ unsigned int g_ermax_enc[NH];         // order-preserving encoded max
__device__ uint32_t g_bits[NN * NWORD];          // mask bitmap [i][j/32]

__device__ __forceinline__ uint32_t smem_u32(const void* p) {
    uint32_t a;
    asm("{ .reg .u64 t; cvta.to.shared.u64 t, %1; cvt.u32.u64 %0, t; }" : "=r"(a) : "l"(p));
    return a;
}

__device__ __forceinline__ unsigned int f2ord(float f) {
    unsigned int u = __float_as_uint(f);
    return (u & 0x80000000u) ? ~u : (u | 0x80000000u);
}
__device__ __forceinline__ float ord2f(unsigned int k) {
    unsigned int u = (k & 0x80000000u) ? (k & 0x7FFFFFFFu) : ~k;
    return __uint_as_float(u);
}

#define MMA16816F16(acc, a0, a1, a2, a3, b0, b1) \
    asm volatile("mma.sync.aligned.m16n8k16.row.col.f32.f16.f16.f32 " \
        "{%0,%1,%2,%3}, {%4,%5,%6,%7}, {%8,%9}, {%0,%1,%2,%3};" \
        : "+f"((acc)[0]), "+f"((acc)[1]), "+f"((acc)[2]), "+f"((acc)[3]) \
        : "r"(a0), "r"(a1), "r"(a2), "r"(a3), "r"(b0), "r"(b1))

#define LDSM4T(r0, r1, r2, r3, a) \
    asm volatile("ldmatrix.sync.aligned.m8n8.x4.trans.shared.b16 {%0,%1,%2,%3}, [%4];" \
        : "=r"(r0), "=r"(r1), "=r"(r2), "=r"(r3) : "r"(a))

#define LDSM4(r0, r1, r2, r3, a) \
    asm volatile("ldmatrix.sync.aligned.m8n8.x4.shared.b16 {%0,%1,%2,%3}, [%4];" \
        : "=r"(r0), "=r"(r1), "=r"(r2), "=r"(r3) : "r"(a))

__device__ __forceinline__ uint32_t pack_hi_f16x2(float a, float b) {
    uint32_t r;
    asm("cvt.rn.f16x2.f32 %0, %1, %2;" : "=r"(r) : "f"(b), "f"(a));
    return r;
}

// ---------------------------------------------------------------------------
// Kernel P: convert h and W to fp16 hi/lo; mask -> bitmap (MLP-16); init ermax.
// ---------------------------------------------------------------------------
__global__ void __launch_bounds__(256) prep_kernel(
    const float* __restrict__ h, const float* __restrict__ W,
    const int* __restrict__ mask)
{
    if (blockIdx.x == 0 && threadIdx.x < NH)
        g_ermax_enc[threadIdx.x] = 0u;  // below every encoded float

    const int stride = gridDim.x * 256;
    for (int i = blockIdx.x * 256 + threadIdx.x; i < NN * FIN / 4; i += stride) {
        float4 v = ((const float4*)h)[i];
        __half hx = __float2half_rn(v.x), hy = __float2half_rn(v.y);
        __half hz = __float2half_rn(v.z), hw = __float2half_rn(v.w);
        uint32_t hi0 = (uint32_t)__half_as_ushort(hx) | ((uint32_t)__half_as_ushort(hy) << 16);
        uint32_t hi1 = (uint32_t)__half_as_ushort(hz) | ((uint32_t)__half_as_ushort(hw) << 16);
        uint32_t lo0 = pack_hi_f16x2(v.x - __half2float(hx), v.y - __half2float(hy));
        uint32_t lo1 = pack_hi_f16x2(v.z - __half2float(hz), v.w - __half2float(hw));
        ((uint2*)g_h16hi)[i] = make_uint2(hi0, hi1);
        ((uint2*)g_h16lo)[i] = make_uint2(lo0, lo1);
    }
    for (int i = blockIdx.x * 256 + threadIdx.x; i < NH * FIN * FO / 4; i += stride) {
        float4 v = ((const float4*)W)[i];
        __half hx = __float2half_rn(v.x), hy = __float2half_rn(v.y);
        __half hz = __float2half_rn(v.z), hw = __float2half_rn(v.w);
        uint32_t hi0 = (uint32_t)__half_as_ushort(hx) | ((uint32_t)__half_as_ushort(hy) << 16);
        uint32_t hi1 = (uint32_t)__half_as_ushort(hz) | ((uint32_t)__half_as_ushort(hw) << 16);
        uint32_t lo0 = pack_hi_f16x2(v.x - __half2float(hx), v.y - __half2float(hy));
        uint32_t lo1 = pack_hi_f16x2(v.z - __half2float(hz), v.w - __half2float(hw));
        ((uint2*)g_w16hi)[i] = make_uint2(hi0, hi1);
        ((uint2*)g_w16lo)[i] = make_uint2(lo0, lo1);
    }
    // mask -> bits: 16 words per warp-iteration (MLP=16)
    {
        const int wid_g = (blockIdx.x * 256 + threadIdx.x) >> 5;
        const int lane  = threadIdx.x & 31;
        const int nwarp = stride >> 5;
        for (int g = wid_g; g < NN * NWORD / 16; g += nwarp) {
            int w0  = 16 * g;
            int row = w0 >> 7;
            int wd  = w0 & (NWORD - 1);
            const int* base = mask + (size_t)row * NN + wd * 32 + lane;
            int m[16];
#pragma unroll
            for (int k = 0; k < 16; k++) m[k] = base[32 * k];
            uint32_t b[16];
#pragma unroll
            for (int k = 0; k < 16; k++) b[k] = __ballot_sync(0xffffffffu, m[k] > 0);
            if (lane == 0) {
#pragma unroll
                for (int s = 0; s < 4; s++)
                    *(uint4*)(g_bits + w0 + 4 * s) =
                        make_uint4(b[4 * s], b[4 * s + 1], b[4 * s + 2], b[4 * s + 3]);
            }
        }
    }
}

// ---------------------------------------------------------------------------
// Kernel A: Wh = h @ W + bW via fp16 HMMA hi/lo split; B fragments pipelined
// one ntp group ahead; fused el/er + per-head er-max.
// ---------------------------------------------------------------------------
#define ASTRIDE 72
#define WH_SMEM (128 * ASTRIDE * 2 * 2 + 64 * ASTRIDE * 2 * 2)

__global__ void __launch_bounds__(256) wh_mma_kernel(
    const float* __restrict__ bW, const float* __restrict__ a_l,
    const float* __restrict__ a_r, const float* __restrict__ bA)
{
    extern __shared__ __align__(16) unsigned short sm[];
    unsigned short* Ah = sm;
    unsigned short* Al = Ah + 128 * ASTRIDE;
    unsigned short* Bh = Al + 128 * ASTRIDE;
    unsigned short* Bl = Bh + 64 * ASTRIDE;
    __shared__ float redmax[8];

    const int t    = threadIdx.x;
    const int warp = t >> 5;
    const int lane = t & 31;
    const int i0   = blockIdx.x * 128;
    const int hh   = blockIdx.y;

    const uint32_t ahB = smem_u32(Ah), alB = smem_u32(Al);
    const uint32_t bhB = smem_u32(Bh), blB = smem_u32(Bl);

    float acc[8][4];
#pragma unroll
    for (int n = 0; n < 8; n++)
#pragma unroll
        for (int j = 0; j < 4; j++) acc[n][j] = 0.f;

    const uint32_t aRow = (uint32_t)(16 * warp + (lane & 15)) * (ASTRIDE * 2) + ((lane & 16) ? 16 : 0);
    const uint32_t bRow = (uint32_t)(lane & 15) * (ASTRIDE * 2) + ((lane & 16) ? 16 : 0);

    for (int ch = 0; ch < FIN / 64; ch++) {
        const int kc = ch * 64;
        __syncthreads();
#pragma unroll
        for (int it = 0; it < 4; it++) {
            int id = t + 256 * it;
            int r = id >> 3, c = id & 7;
            size_t src = (size_t)(i0 + r) * FIN + kc + c * 8;
            *(uint4*)&Ah[r * ASTRIDE + c * 8] = *(const uint4*)(g_h16hi + src);
            *(uint4*)&Al[r * ASTRIDE + c * 8] = *(const uint4*)(g_h16lo + src);
        }
#pragma unroll
        for (int it = 0; it < 2; it++) {
            int id = t + 256 * it;
            int r = id >> 3, c = id & 7;
            size_t src = ((size_t)hh * FIN + kc + r) * FO + c * 8;
            *(uint4*)&Bh[r * ASTRIDE + c * 8] = *(const uint4*)(g_w16hi + src);
            *(uint4*)&Bl[r * ASTRIDE + c * 8] = *(const uint4*)(g_w16lo + src);
        }
        __syncthreads();

#pragma unroll
        for (int kt = 0; kt < 4; kt++) {
            uint32_t ah0, ah1, ah2, ah3, al0, al1, al2, al3;
            LDSM4(ah0, ah1, ah2, ah3, ahB + aRow + kt * 32);
            LDSM4(al0, al1, al2, al3, alB + aRow + kt * 32);
            const uint32_t kOff = (uint32_t)(16 * kt) * (ASTRIDE * 2) + bRow;

            uint32_t bhc[4], blc[4], bhn[4], bln[4];
            LDSM4T(bhc[0], bhc[1], bhc[2], bhc[3], bhB + kOff);
            LDSM4T(blc[0], blc[1], blc[2], blc[3], blB + kOff);
#pragma unroll
            for (int ntp = 0; ntp < 4; ntp++) {
                if (ntp < 3) {
                    LDSM4T(bhn[0], bhn[1], bhn[2], bhn[3], bhB + kOff + 32 * (ntp + 1));
                    LDSM4T(bln[0], bln[1], bln[2], bln[3], blB + kOff + 32 * (ntp + 1));
                }
                MMA16816F16(acc[2 * ntp],     ah0, ah1, ah2, ah3, bhc[0], bhc[1]);
                MMA16816F16(acc[2 * ntp],     al0, al1, al2, al3, bhc[0], bhc[1]);
                MMA16816F16(acc[2 * ntp],     ah0, ah1, ah2, ah3, blc[0], blc[1]);
                MMA16816F16(acc[2 * ntp + 1], ah0, ah1, ah2, ah3, bhc[2], bhc[3]);
                MMA16816F16(acc[2 * ntp + 1], al0, al1, al2, al3, bhc[2], bhc[3]);
                MMA16816F16(acc[2 * ntp + 1], ah0, ah1, ah2, ah3, blc[2], blc[3]);
                if (ntp < 3) {
#pragma unroll
                    for (int z = 0; z < 4; z++) { bhc[z] = bhn[z]; blc[z] = bln[z]; }
                }
            }
        }
    }

    // ---- epilogue: bias, store fp16 Wh, fused el/er, er-max ----
    const int q  = lane >> 2;
    const int c2 = 2 * (lane & 3);
    const int r0 = i0 + 16 * warp + q;
    const int r1 = r0 + 8;

    float dl0 = 0.f, dr0 = 0.f, dl1 = 0.f, dr1 = 0.f;
#pragma unroll
    for (int nt = 0; nt < 8; nt++) {
        int col = 8 * nt + c2;
        float2 bw = *(const float2*)(bW + hh * FO + col);
        float2 al = *(const float2*)(a_l + hh * FO + col);
        float2 ar = *(const float2*)(a_r + hh * FO + col);
        float v00 = acc[nt][0] + bw.x, v01 = acc[nt][1] + bw.y;
        float v10 = acc[nt][2] + bw.x, v11 = acc[nt][3] + bw.y;
        *(uint32_t*)(g_wh16 + ((size_t)hh * NN + r0) * FO + col) = pack_hi_f16x2(v00, v01);
        *(uint32_t*)(g_wh16 + ((size_t)hh * NN + r1) * FO + col) = pack_hi_f16x2(v10, v11);
        dl0 += v00 * al.x + v01 * al.y;
        dr0 += v00 * ar.x + v01 * ar.y;
        dl1 += v10 * al.x + v11 * al.y;
        dr1 += v10 * ar.x + v11 * ar.y;
    }
#pragma unroll
    for (int off = 1; off < 4; off <<= 1) {
        dl0 += __shfl_xor_sync(0xffffffffu, dl0, off);
        dr0 += __shfl_xor_sync(0xffffffffu, dr0, off);
        dl1 += __shfl_xor_sync(0xffffffffu, dl1, off);
        dr1 += __shfl_xor_sync(0xffffffffu, dr1, off);
    }
    float er0s = dr0 * LOG2E, er1s = dr1 * LOG2E;
    if ((lane & 3) == 0) {
        float ba = bA[hh];
        g_el[hh * NN + r0] = (dl0 + ba) * LOG2E;
        g_er[hh * NN + r0] = er0s;
        g_el[hh * NN + r1] = (dl1 + ba) * LOG2E;
        g_er[hh * NN + r1] = er1s;
    }
    float wm = fmaxf(er0s, er1s);
#pragma unroll
    for (int off = 4; off < 32; off <<= 1)
        wm = fmaxf(wm, __shfl_xor_sync(0xffffffffu, wm, off));
    if (lane == 0) redmax[warp] = wm;
    __syncthreads();
    if (t == 0) {
        float m = redmax[0];
#pragma unroll
        for (int w = 1; w < 8; w++) m = fmaxf(m, redmax[w]);
        atomicMax(&g_ermax_enc[hh], f2ord(m));
    }
}

// ---------------------------------------------------------------------------
// Kernel C: fp16 HMMA flash-GAT, 128-wide j tiles; scores SW-pipelined one kt
// ahead; B fragments pipelined one ntp group ahead.
// ---------------------------------------------------------------------------
__device__ __forceinline__ float elu(float v) {
    return v > 0.f ? v : (__expf(v) - 1.f);
}

__device__ __forceinline__ uint32_t pscore2(float2 ed, float2 er, uint32_t b2) {
    float x0 = ed.x + er.x;
    float a0 = fmaxf(x0, fmaf(ALPHA, x0, ed.y));
    float x1 = ed.x + er.y;
    float a1 = fmaxf(x1, fmaf(ALPHA, x1, ed.y));
    uint32_t ph, pe;
    asm("cvt.rn.f16x2.f32 %0, %1, %2;" : "=r"(ph) : "f"(a1), "f"(a0));
    asm("ex2.approx.f16x2 %0, %1;" : "=r"(pe) : "r"(ph));
    uint32_t msk = ((b2 & 1u) ? 0x0000FFFFu : 0u) | ((b2 & 2u) ? 0xFFFF0000u : 0u);
    return pe & msk;
}

#define BSTRIDE 72
#define JT 128
#define ATTN_BS_BYTES (2 * JT * BSTRIDE * 2)            /* 36864 */
#define ATTN_SMEM (ATTN_BS_BYTES + 1024 + NN * 4)       /* 54272 */

__global__ void __launch_bounds__(256, 2) gat_attn_mma_kernel(float* __restrict__ out)
{
    extern __shared__ __align__(16) char dsm[];
    unsigned short* Bs = (unsigned short*)dsm;
    float2* els2 = (float2*)(dsm + ATTN_BS_BYTES);
    float* ers = (float*)(dsm + ATTN_BS_BYTES + 1024);

    const int t    = threadIdx.x;
    const int warp = t >> 5;
    const int lane = t & 31;
    const int i0   = blockIdx.x * 128;
    const int hh   = blockIdx.y;

    {
        const float4* src = (const float4*)(g_er + hh * NN);
#pragma unroll
        for (int it = 0; it < NN / 4 / 256; it++)
            ((float4*)ers)[t + 256 * it] = src[t + 256 * it];
    }

    if (t < 128) {
        float e = g_el[hh * NN + i0 + t];
        float z = e + ord2f(g_ermax_enc[hh]);
        float c = fmaxf(z, ALPHA * z);
        els2[t] = make_float2(e - c, (ALPHA - 1.f) * c);
    }

    const int q  = lane >> 2;
    const int c2 = 2 * (lane & 3);
    const int rw0 = 16 * warp + q;

    const unsigned short* gwh = g_wh16 + (size_t)hh * NN * FO;
    const uint32_t* bitbase =
        g_bits + (size_t)(i0 + 16 * warp + (lane >> 1)) * NWORD + (lane & 1) * 2;

    const uint32_t bBase = smem_u32(Bs);
    const uint32_t lrowOff = (uint32_t)(lane & 15) * (BSTRIDE * 2) + ((lane & 16) ? 16 : 0);

    const int lk0 = t >> 3, lc0 = t & 7;
    const int lk1 = (t + 256) >> 3, lc1 = t & 7;

    float acc[8][4];
#pragma unroll
    for (int n = 0; n < 8; n++)
#pragma unroll
        for (int j = 0; j < 4; j++) acc[n][j] = 0.f;
    float accd[4] = {0.f, 0.f, 0.f, 0.f};
    const uint32_t ONES = 0x3C003C00u;

    {
#pragma unroll
        for (int hf = 0; hf < 2; hf++) {
            uint4 va = *(const uint4*)(gwh + (size_t)(hf * 64 + lk0) * FO + lc0 * 8);
            uint4 vb = *(const uint4*)(gwh + (size_t)(hf * 64 + lk1) * FO + lc1 * 8);
            *(uint4*)&Bs[(hf * 64 + lk0) * BSTRIDE + lc0 * 8] = va;
            *(uint4*)&Bs[(hf * 64 + lk1) * BSTRIDE + lc1 * 8] = vb;
        }
    }
    uint2 bvNext = *(const uint2*)(bitbase);
    __syncthreads();

    const float2 ec0 = els2[rw0];
    const float2 ec1 = els2[rw0 + 8];

    uint32_t w0[4], w1[4];
    auto distrib = [&](uint2 bv) {
        w0[0] = __shfl_sync(0xffffffffu, bv.x, 2 * q);
        w0[1] = __shfl_sync(0xffffffffu, bv.y, 2 * q);
        w0[2] = __shfl_sync(0xffffffffu, bv.x, 2 * q + 1);
        w0[3] = __shfl_sync(0xffffffffu, bv.y, 2 * q + 1);
        w1[0] = __shfl_sync(0xffffffffu, bv.x, 2 * q + 16);
        w1[1] = __shfl_sync(0xffffffffu, bv.y, 2 * q + 16);
        w1[2] = __shfl_sync(0xffffffffu, bv.x, 2 * q + 17);
        w1[3] = __shfl_sync(0xffffffffu, bv.y, 2 * q + 17);
    };

    auto scoreblk = [&](int jb0, int kt, uint32_t* a) {
        const int jb = jb0 + 16 * kt + c2;
        float2 e0 = *(const float2*)(ers + jb);
        float2 e1 = *(const float2*)(ers + jb + 8);
        const int wi = kt >> 1;
        const int sb = (kt & 1) * 16;
        uint32_t v0 = w0[wi] >> (sb + c2);
        uint32_t v1 = w1[wi] >> (sb + c2);
        a[0] = pscore2(ec0, e0, v0 & 3u);
        a[1] = pscore2(ec1, e0, v1 & 3u);
        a[2] = pscore2(ec0, e1, (v0 >> 8) & 3u);
        a[3] = pscore2(ec1, e1, (v1 >> 8) & 3u);
    };

    distrib(bvNext);
    uint32_t aF[4];
    scoreblk(0, 0, aF);

    for (int tile = 0; tile < NN / JT; tile++) {
        const int j0 = tile * JT;
        const int cur = tile & 1;
        const bool last = (tile == NN / JT - 1);

        if (!last) bvNext = *(const uint2*)(bitbase + (tile + 1) * 4);

        uint4 na, nb;
        if (!last) {
            const unsigned short* src = gwh + (size_t)(j0 + JT) * FO;
            na = *(const uint4*)(src + (size_t)lk0 * FO + lc0 * 8);
            nb = *(const uint4*)(src + (size_t)lk1 * FO + lc1 * 8);
        }

        const uint32_t bufOff = bBase + cur * (JT * BSTRIDE * 2) + lrowOff;
        unsigned short* dst = &Bs[(cur ^ 1) * JT * BSTRIDE];

#pragma unroll
        for (int kt = 0; kt < 8; kt++) {
            uint32_t aN[4];
            if (kt < 7)
                scoreblk(j0, kt + 1, aN);

            const uint32_t kOff = bufOff + (uint32_t)(16 * kt) * (BSTRIDE * 2);

            uint32_t bc[4], bn[4];
            LDSM4T(bc[0], bc[1], bc[2], bc[3], kOff);
#pragma unroll
            for (int ntp = 0; ntp < 4; ntp++) {
                if (ntp < 3)
                    LDSM4T(bn[0], bn[1], bn[2], bn[3], kOff + 32 * (ntp + 1));
                MMA16816F16(acc[2 * ntp],     aF[0], aF[1], aF[2], aF[3], bc[0], bc[1]);
                MMA16816F16(acc[2 * ntp + 1], aF[0], aF[1], aF[2], aF[3], bc[2], bc[3]);
                if (ntp < 3) {
#pragma unroll
                    for (int z = 0; z < 4; z++) bc[z] = bn[z];
                }
            }
            MMA16816F16(accd, aF[0], aF[1], aF[2], aF[3], ONES, ONES);

            if (kt == 3 && !last) {
                *(uint4*)&dst[lk0 * BSTRIDE + lc0 * 8] = na;
                *(uint4*)&dst[lk1 * BSTRIDE + lc1 * 8] = nb;
                const unsigned short* src = gwh + (size_t)(j0 + JT + 64) * FO;
                na = *(const uint4*)(src + (size_t)lk0 * FO + lc0 * 8);
                nb = *(const uint4*)(src + (size_t)lk1 * FO + lc1 * 8);
            }

            if (kt < 7) {
                aF[0] = aN[0]; aF[1] = aN[1]; aF[2] = aN[2]; aF[3] = aN[3];
            }
        }

        if (!last) {
            *(uint4*)&dst[(64 + lk0) * BSTRIDE + lc0 * 8] = na;
            *(uint4*)&dst[(64 + lk1) * BSTRIDE + lc1 * 8] = nb;
            distrib(bvNext);
            scoreblk(j0 + JT, 0, aF);
        }
        __syncthreads();
    }

    const float inv0 = 1.f / accd[0];
    const float inv1 = 1.f / accd[2];

    float* ob0 = out + (size_t)(i0 + rw0) * OUTW + hh * FO + c2;
    float* ob1 = ob0 + (size_t)8 * OUTW;
#pragma unroll
    for (int nt = 0; nt < 8; nt++) {
        float2 v0 = make_float2(elu(acc[nt][0] * inv0), elu(acc[nt][1] * inv0));
        float2 v1 = make_float2(elu(acc[nt][2] * inv1), elu(acc[nt][3] * inv1));
        *(float2*)(ob0 + 8 * nt) = v0;
        *(float2*)(ob1 + 8 * nt) = v1;
    }
}

// ---------------------------------------------------------------------------
extern "C" void kernel_launch(void* const* d_in, const int* in_sizes, int n_in,
                              void* d_out, int out_size)
{
    const float* h    = (const float*)d_in[0];  // [N, FIN]
    const int*   mask = (const int*)  d_in[1];  // [N, N]
    const float* W    = (const float*)d_in[2];  // [H, FIN, FO]
    const float* bW   = (const float*)d_in[3];  // [H, FO]
    const float* a_l  = (const float*)d_in[4];  // [H, FO]
    const float* a_r  = (const float*)d_in[5];  // [H, FO]
    const float* bA   = (const float*)d_in[6];  // [H]
    float* out = (float*)d_out;                 // [N, H*FO]

    cudaFuncSetAttribute(wh_mma_kernel,
                         cudaFuncAttributeMaxDynamicSharedMemorySize, WH_SMEM);
    cudaFuncSetAttribute(gat_attn_mma_kernel,
                         cudaFuncAttributeMaxDynamicSharedMemorySize, ATTN_SMEM);

    prep_kernel<<<1024, 256>>>(h, W, mask);
    wh_mma_kernel<<<dim3(NN / 128, NH), 256, WH_SMEM>>>(bW, a_l, a_r, bA);
    gat_attn_mma_kernel<<<dim3(NN / 128, NH), 256, ATTN_SMEM>>>(out);
}

// round 14
// speedup vs baseline: 1.9064x; 1.0156x over previous
#include <cuda_runtime.h>
#include <cuda_fp16.h>
#include <cstdint>

#define NN 4096
#define FIN 512
#define FO 64
#define NH 8
#define ALPHA 0.2f
#define OUTW (NH * FO)  /* 512 */
#define LOG2E 1.4426950408889634f
#define NWORD (NN / 32)  /* 128 */

// ---------------------------------------------------------------------------
// Scratch (static device globals)
// ---------------------------------------------------------------------------
__device__ unsigned short g_h16hi[NN * FIN];     // fp16 hi of h, [n][k]
__device__ unsigned short g_h16lo[NN * FIN];     // fp16 lo of h, [n][k]
__device__ unsigned short g_w16hi[NH * FIN * FO];// fp16 hi of W, [h][k][n]
__device__ unsigned short g_w16lo[NH * FIN * FO];
__device__ unsigned short g_wh16[NH * NN * FO];  // fp16 Wh, [h][n][o]
__device__ float g_el[NH * NN];                  // el * log2e (incl bA)
__device__ float g_er[NH * NN];                  // er * log2e
__device__ unsigned int g_ermax_enc[NH];         // order-preserving encoded max
__device__ uint32_t g_bits[NN * NWORD];          // mask bitmap [i][j/32]

__device__ __forceinline__ uint32_t smem_u32(const void* p) {
    uint32_t a;
    asm("{ .reg .u64 t; cvta.to.shared.u64 t, %1; cvt.u32.u64 %0, t; }" : "=r"(a) : "l"(p));
    return a;
}

__device__ __forceinline__ unsigned int f2ord(float f) {
    unsigned int u = __float_as_uint(f);
    return (u & 0x80000000u) ? ~u : (u | 0x80000000u);
}
__device__ __forceinline__ float ord2f(unsigned int k) {
    unsigned int u = (k & 0x80000000u) ? (k & 0x7FFFFFFFu) : ~k;
    return __uint_as_float(u);
}

#define MMA16816F16(acc, a0, a1, a2, a3, b0, b1) \
    asm volatile("mma.sync.aligned.m16n8k16.row.col.f32.f16.f16.f32 " \
        "{%0,%1,%2,%3}, {%4,%5,%6,%7}, {%8,%9}, {%0,%1,%2,%3};" \
        : "+f"((acc)[0]), "+f"((acc)[1]), "+f"((acc)[2]), "+f"((acc)[3]) \
        : "r"(a0), "r"(a1), "r"(a2), "r"(a3), "r"(b0), "r"(b1))

#define LDSM4T(r0, r1, r2, r3, a) \
    asm volatile("ldmatrix.sync.aligned.m8n8.x4.trans.shared.b16 {%0,%1,%2,%3}, [%4];" \
        : "=r"(r0), "=r"(r1), "=r"(r2), "=r"(r3) : "r"(a))

#define LDSM4(r0, r1, r2, r3, a) \
    asm volatile("ldmatrix.sync.aligned.m8n8.x4.shared.b16 {%0,%1,%2,%3}, [%4];" \
        : "=r"(r0), "=r"(r1), "=r"(r2), "=r"(r3) : "r"(a))

__device__ __forceinline__ uint32_t pack_hi_f16x2(float a, float b) {
    uint32_t r;
    asm("cvt.rn.f16x2.f32 %0, %1, %2;" : "=r"(r) : "f"(b), "f"(a));
    return r;
}

// ---------------------------------------------------------------------------
// Kernel P: convert h and W to fp16 hi/lo; mask -> bitmap (MLP-16); init ermax.
// ---------------------------------------------------------------------------
__global__ void __launch_bounds__(256) prep_kernel(
    const float* __restrict__ h, const float* __restrict__ W,
    const int* __restrict__ mask)
{
    if (blockIdx.x == 0 && threadIdx.x < NH)
        g_ermax_enc[threadIdx.x] = 0u;  // below every encoded float

    const int stride = gridDim.x * 256;
    for (int i = blockIdx.x * 256 + threadIdx.x; i < NN * FIN / 4; i += stride) {
        float4 v = ((const float4*)h)[i];
        __half hx = __float2half_rn(v.x), hy = __float2half_rn(v.y);
        __half hz = __float2half_rn(v.z), hw = __float2half_rn(v.w);
        uint32_t hi0 = (uint32_t)__half_as_ushort(hx) | ((uint32_t)__half_as_ushort(hy) << 16);
        uint32_t hi1 = (uint32_t)__half_as_ushort(hz) | ((uint32_t)__half_as_ushort(hw) << 16);
        uint32_t lo0 = pack_hi_f16x2(v.x - __half2float(hx), v.y - __half2float(hy));
        uint32_t lo1 = pack_hi_f16x2(v.z - __half2float(hz), v.w - __half2float(hw));
        ((uint2*)g_h16hi)[i] = make_uint2(hi0, hi1);
        ((uint2*)g_h16lo)[i] = make_uint2(lo0, lo1);
    }
    for (int i = blockIdx.x * 256 + threadIdx.x; i < NH * FIN * FO / 4; i += stride) {
        float4 v = ((const float4*)W)[i];
        __half hx = __float2half_rn(v.x), hy = __float2half_rn(v.y);
        __half hz = __float2half_rn(v.z), hw = __float2half_rn(v.w);
        uint32_t hi0 = (uint32_t)__half_as_ushort(hx) | ((uint32_t)__half_as_ushort(hy) << 16);
        uint32_t hi1 = (uint32_t)__half_as_ushort(hz) | ((uint32_t)__half_as_ushort(hw) << 16);
        uint32_t lo0 = pack_hi_f16x2(v.x - __half2float(hx), v.y - __half2float(hy));
        uint32_t lo1 = pack_hi_f16x2(v.z - __half2float(hz), v.w - __half2float(hw));
        ((uint2*)g_w16hi)[i] = make_uint2(hi0, hi1);
        ((uint2*)g_w16lo)[i] = make_uint2(lo0, lo1);
    }
    // mask -> bits: 16 words per warp-iteration (MLP=16)
    {
        const int wid_g = (blockIdx.x * 256 + threadIdx.x) >> 5;
        const int lane  = threadIdx.x & 31;
        const int nwarp = stride >> 5;
        for (int g = wid_g; g < NN * NWORD / 16; g += nwarp) {
            int w0  = 16 * g;
            int row = w0 >> 7;
            int wd  = w0 & (NWORD - 1);
            const int* base = mask + (size_t)row * NN + wd * 32 + lane;
            int m[16];
#pragma unroll
            for (int k = 0; k < 16; k++) m[k] = base[32 * k];
            uint32_t b[16];
#pragma unroll
            for (int k = 0; k < 16; k++) b[k] = __ballot_sync(0xffffffffu, m[k] > 0);
            if (lane == 0) {
#pragma unroll
                for (int s = 0; s < 4; s++)
                    *(uint4*)(g_bits + w0 + 4 * s) =
                        make_uint4(b[4 * s], b[4 * s + 1], b[4 * s + 2], b[4 * s + 3]);
            }
        }
    }
}

// ---------------------------------------------------------------------------
// Kernel A: Wh = h @ W + bW via fp16 HMMA hi/lo split; B fragments pipelined
// one ntp group ahead; fused el/er + per-head er-max.
// ---------------------------------------------------------------------------
#define ASTRIDE 72
#define WH_SMEM (128 * ASTRIDE * 2 * 2 + 64 * ASTRIDE * 2 * 2)

__global__ void __launch_bounds__(256) wh_mma_kernel(
    const float* __restrict__ bW, const float* __restrict__ a_l,
    const float* __restrict__ a_r, const float* __restrict__ bA)
{
    extern __shared__ __align__(16) unsigned short sm[];
    unsigned short* Ah = sm;
    unsigned short* Al = Ah + 128 * ASTRIDE;
    unsigned short* Bh = Al + 128 * ASTRIDE;
    unsigned short* Bl = Bh + 64 * ASTRIDE;
    __shared__ float redmax[8];

    const int t    = threadIdx.x;
    const int warp = t >> 5;
    const int lane = t & 31;
    const int i0   = blockIdx.x * 128;
    const int hh   = blockIdx.y;

    const uint32_t ahB = smem_u32(Ah), alB = smem_u32(Al);
    const uint32_t bhB = smem_u32(Bh), blB = smem_u32(Bl);

    float acc[8][4];
#pragma unroll
    for (int n = 0; n < 8; n++)
#pragma unroll
        for (int j = 0; j < 4; j++) acc[n][j] = 0.f;

    const uint32_t aRow = (uint32_t)(16 * warp + (lane & 15)) * (ASTRIDE * 2) + ((lane & 16) ? 16 : 0);
    const uint32_t bRow = (uint32_t)(lane & 15) * (ASTRIDE * 2) + ((lane & 16) ? 16 : 0);

    for (int ch = 0; ch < FIN / 64; ch++) {
        const int kc = ch * 64;
        __syncthreads();
#pragma unroll
        for (int it = 0; it < 4; it++) {
            int id = t + 256 * it;
            int r = id >> 3, c = id & 7;
            size_t src = (size_t)(i0 + r) * FIN + kc + c * 8;
            *(uint4*)&Ah[r * ASTRIDE + c * 8] = *(const uint4*)(g_h16hi + src);
            *(uint4*)&Al[r * ASTRIDE + c * 8] = *(const uint4*)(g_h16lo + src);
        }
#pragma unroll
        for (int it = 0; it < 2; it++) {
            int id = t + 256 * it;
            int r = id >> 3, c = id & 7;
            size_t src = ((size_t)hh * FIN + kc + r) * FO + c * 8;
            *(uint4*)&Bh[r * ASTRIDE + c * 8] = *(const uint4*)(g_w16hi + src);
            *(uint4*)&Bl[r * ASTRIDE + c * 8] = *(const uint4*)(g_w16lo + src);
        }
        __syncthreads();

#pragma unroll
        for (int kt = 0; kt < 4; kt++) {
            uint32_t ah0, ah1, ah2, ah3, al0, al1, al2, al3;
            LDSM4(ah0, ah1, ah2, ah3, ahB + aRow + kt * 32);
            LDSM4(al0, al1, al2, al3, alB + aRow + kt * 32);
            const uint32_t kOff = (uint32_t)(16 * kt) * (ASTRIDE * 2) + bRow;

            uint32_t bhc[4], blc[4], bhn[4], bln[4];
            LDSM4T(bhc[0], bhc[1], bhc[2], bhc[3], bhB + kOff);
            LDSM4T(blc[0], blc[1], blc[2], blc[3], blB + kOff);
#pragma unroll
            for (int ntp = 0; ntp < 4; ntp++) {
                if (ntp < 3) {
                    LDSM4T(bhn[0], bhn[1], bhn[2], bhn[3], bhB + kOff + 32 * (ntp + 1));
                    LDSM4T(bln[0], bln[1], bln[2], bln[3], blB + kOff + 32 * (ntp + 1));
                }
                MMA16816F16(acc[2 * ntp],     ah0, ah1, ah2, ah3, bhc[0], bhc[1]);
                MMA16816F16(acc[2 * ntp],     al0, al1, al2, al3, bhc[0], bhc[1]);
                MMA16816F16(acc[2 * ntp],     ah0, ah1, ah2, ah3, blc[0], blc[1]);
                MMA16816F16(acc[2 * ntp + 1], ah0, ah1, ah2, ah3, bhc[2], bhc[3]);
                MMA16816F16(acc[2 * ntp + 1], al0, al1, al2, al3, bhc[2], bhc[3]);
                MMA16816F16(acc[2 * ntp + 1], ah0, ah1, ah2, ah3, blc[2], blc[3]);
                if (ntp < 3) {
#pragma unroll
                    for (int z = 0; z < 4; z++) { bhc[z] = bhn[z]; blc[z] = bln[z]; }
                }
            }
        }
    }

    // ---- epilogue: bias, store fp16 Wh, fused el/er, er-max ----
    const int q  = lane >> 2;
    const int c2 = 2 * (lane & 3);
    const int r0 = i0 + 16 * warp + q;
    const int r1 = r0 + 8;

    float dl0 = 0.f, dr0 = 0.f, dl1 = 0.f, dr1 = 0.f;
#pragma unroll
    for (int nt = 0; nt < 8; nt++) {
        int col = 8 * nt + c2;
        float2 bw = *(const float2*)(bW + hh * FO + col);
        float2 al = *(const float2*)(a_l + hh * FO + col);
        float2 ar = *(const float2*)(a_r + hh * FO + col);
        float v00 = acc[nt][0] + bw.x, v01 = acc[nt][1] + bw.y;
        float v10 = acc[nt][2] + bw.x, v11 = acc[nt][3] + bw.y;
        *(uint32_t*)(g_wh16 + ((size_t)hh * NN + r0) * FO + col) = pack_hi_f16x2(v00, v01);
        *(uint32_t*)(g_wh16 + ((size_t)hh * NN + r1) * FO + col) = pack_hi_f16x2(v10, v11);
        dl0 += v00 * al.x + v01 * al.y;
        dr0 += v00 * ar.x + v01 * ar.y;
        dl1 += v10 * al.x + v11 * al.y;
        dr1 += v10 * ar.x + v11 * ar.y;
    }
#pragma unroll
    for (int off = 1; off < 4; off <<= 1) {
        dl0 += __shfl_xor_sync(0xffffffffu, dl0, off);
        dr0 += __shfl_xor_sync(0xffffffffu, dr0, off);
        dl1 += __shfl_xor_sync(0xffffffffu, dl1, off);
        dr1 += __shfl_xor_sync(0xffffffffu, dr1, off);
    }
    float er0s = dr0 * LOG2E, er1s = dr1 * LOG2E;
    if ((lane & 3) == 0) {
        float ba = bA[hh];
        g_el[hh * NN + r0] = (dl0 + ba) * LOG2E;
        g_er[hh * NN + r0] = er0s;
        g_el[hh * NN + r1] = (dl1 + ba) * LOG2E;
        g_er[hh * NN + r1] = er1s;
    }
    float wm = fmaxf(er0s, er1s);
#pragma unroll
    for (int off = 4; off < 32; off <<= 1)
        wm = fmaxf(wm, __shfl_xor_sync(0xffffffffu, wm, off));
    if (lane == 0) redmax[warp] = wm;
    __syncthreads();
    if (t == 0) {
        float m = redmax[0];
#pragma unroll
        for (int w = 1; w < 8; w++) m = fmaxf(m, redmax[w]);
        atomicMax(&g_ermax_enc[hh], f2ord(m));
    }
}

// ---------------------------------------------------------------------------
// Kernel C: fp16 HMMA flash-GAT, 128-wide j tiles; scores SW-pipelined one kt
// ahead (hides the f16x2 chain latency); f16x2 fused score math (fewer ops).
// ---------------------------------------------------------------------------
__device__ __forceinline__ float elu(float v) {
    return v > 0.f ? v : (__expf(v) - 1.f);
}

#define ALPHA2_F16 0x32663266u  /* (0.2, 0.2) fp16x2 */

// Two numerators: x in f32 adds, then packed f16x2 lrelu+ex2 chain.
__device__ __forceinline__ uint32_t pscore2(float elp, uint32_t d2, float2 er, uint32_t b2) {
    float x0 = elp + er.x;
    float x1 = elp + er.y;
    uint32_t xh, yh, mh, pe;
    asm("cvt.rn.f16x2.f32 %0, %1, %2;" : "=r"(xh) : "f"(x1), "f"(x0));
    asm("fma.rn.f16x2 %0, %1, %2, %3;" : "=r"(yh) : "r"(ALPHA2_F16), "r"(xh), "r"(d2));
    asm("max.f16x2 %0, %1, %2;" : "=r"(mh) : "r"(xh), "r"(yh));
    asm("ex2.approx.f16x2 %0, %1;" : "=r"(pe) : "r"(mh));
    uint32_t msk = ((b2 & 1u) ? 0x0000FFFFu : 0u) | ((b2 & 2u) ? 0xFFFF0000u : 0u);
    return pe & msk;
}

#define BSTRIDE 72
#define JT 128
#define ATTN_BS_BYTES (2 * JT * BSTRIDE * 2)            /* 36864 */
#define ATTN_SMEM (ATTN_BS_BYTES + 1024 + NN * 4)       /* 54272 */

__global__ void __launch_bounds__(256, 2) gat_attn_mma_kernel(float* __restrict__ out)
{
    extern __shared__ __align__(16) char dsm[];
    unsigned short* Bs = (unsigned short*)dsm;
    float2* els2 = (float2*)(dsm + ATTN_BS_BYTES);
    float* ers = (float*)(dsm + ATTN_BS_BYTES + 1024);

    const int t    = threadIdx.x;
    const int warp = t >> 5;
    const int lane = t & 31;
    const int i0   = blockIdx.x * 128;
    const int hh   = blockIdx.y;

    {
        const float4* src = (const float4*)(g_er + hh * NN);
#pragma unroll
        for (int it = 0; it < NN / 4 / 256; it++)
            ((float4*)ers)[t + 256 * it] = src[t + 256 * it];
    }

    if (t < 128) {
        float e = g_el[hh * NN + i0 + t];
        float z = e + ord2f(g_ermax_enc[hh]);
        float c = fmaxf(z, ALPHA * z);
        float d = (ALPHA - 1.f) * c;
        __half hd = __float2half_rn(d);
        uint32_t d2 = (uint32_t)__half_as_ushort(hd);
        d2 |= d2 << 16;
        els2[t] = make_float2(e - c, __uint_as_float(d2));
    }

    const int q  = lane >> 2;
    const int c2 = 2 * (lane & 3);
    const int rw0 = 16 * warp + q;

    const unsigned short* gwh = g_wh16 + (size_t)hh * NN * FO;
    const uint32_t* bitbase =
        g_bits + (size_t)(i0 + 16 * warp + (lane >> 1)) * NWORD + (lane & 1) * 2;

    const uint32_t bBase = smem_u32(Bs);
    const uint32_t lrowOff = (uint32_t)(lane & 15) * (BSTRIDE * 2) + ((lane & 16) ? 16 : 0);

    const int lk0 = t >> 3, lc0 = t & 7;
    const int lk1 = (t + 256) >> 3, lc1 = t & 7;

    float acc[8][4];
#pragma unroll
    for (int n = 0; n < 8; n++)
#pragma unroll
        for (int j = 0; j < 4; j++) acc[n][j] = 0.f;
    float accd[4] = {0.f, 0.f, 0.f, 0.f};
    const uint32_t ONES = 0x3C003C00u;

    {
#pragma unroll
        for (int hf = 0; hf < 2; hf++) {
            uint4 va = *(const uint4*)(gwh + (size_t)(hf * 64 + lk0) * FO + lc0 * 8);
            uint4 vb = *(const uint4*)(gwh + (size_t)(hf * 64 + lk1) * FO + lc1 * 8);
            *(uint4*)&Bs[(hf * 64 + lk0) * BSTRIDE + lc0 * 8] = va;
            *(uint4*)&Bs[(hf * 64 + lk1) * BSTRIDE + lc1 * 8] = vb;
        }
    }
    uint2 bvNext = *(const uint2*)(bitbase);
    __syncthreads();

    const float2 ec0 = els2[rw0];
    const float2 ec1 = els2[rw0 + 8];
    const float elp0 = ec0.x, elp1 = ec1.x;
    const uint32_t d20 = __float_as_uint(ec0.y), d21 = __float_as_uint(ec1.y);

    uint32_t w0[4], w1[4];
    auto distrib = [&](uint2 bv) {
        w0[0] = __shfl_sync(0xffffffffu, bv.x, 2 * q);
        w0[1] = __shfl_sync(0xffffffffu, bv.y, 2 * q);
        w0[2] = __shfl_sync(0xffffffffu, bv.x, 2 * q + 1);
        w0[3] = __shfl_sync(0xffffffffu, bv.y, 2 * q + 1);
        w1[0] = __shfl_sync(0xffffffffu, bv.x, 2 * q + 16);
        w1[1] = __shfl_sync(0xffffffffu, bv.y, 2 * q + 16);
        w1[2] = __shfl_sync(0xffffffffu, bv.x, 2 * q + 17);
        w1[3] = __shfl_sync(0xffffffffu, bv.y, 2 * q + 17);
    };

    auto scoreblk = [&](int jb0, int kt, uint32_t* a) {
        const int jb = jb0 + 16 * kt + c2;
        float2 e0 = *(const float2*)(ers + jb);
        float2 e1 = *(const float2*)(ers + jb + 8);
        const int wi = kt >> 1;
        const int sb = (kt & 1) * 16;
        uint32_t v0 = w0[wi] >> (sb + c2);
        uint32_t v1 = w1[wi] >> (sb + c2);
        a[0] = pscore2(elp0, d20, e0, v0 & 3u);
        a[1] = pscore2(elp1, d21, e0, v1 & 3u);
        a[2] = pscore2(elp0, d20, e1, (v0 >> 8) & 3u);
        a[3] = pscore2(elp1, d21, e1, (v1 >> 8) & 3u);
    };

    distrib(bvNext);
    uint32_t aF[4];
    scoreblk(0, 0, aF);

    for (int tile = 0; tile < NN / JT; tile++) {
        const int j0 = tile * JT;
        const int cur = tile & 1;
        const bool last = (tile == NN / JT - 1);

        if (!last) bvNext = *(const uint2*)(bitbase + (tile + 1) * 4);

        uint4 na, nb;
        if (!last) {
            const unsigned short* src = gwh + (size_t)(j0 + JT) * FO;
            na = *(const uint4*)(src + (size_t)lk0 * FO + lc0 * 8);
            nb = *(const uint4*)(src + (size_t)lk1 * FO + lc1 * 8);
        }

        const uint32_t bufOff = bBase + cur * (JT * BSTRIDE * 2) + lrowOff;
        unsigned short* dst = &Bs[(cur ^ 1) * JT * BSTRIDE];

#pragma unroll
        for (int kt = 0; kt < 8; kt++) {
            uint32_t aN[4];
            if (kt < 7)
                scoreblk(j0, kt + 1, aN);

            const uint32_t kOff = bufOff + (uint32_t)(16 * kt) * (BSTRIDE * 2);

            uint32_t bc[4], bn[4];
            LDSM4T(bc[0], bc[1], bc[2], bc[3], kOff);
#pragma unroll
            for (int ntp = 0; ntp < 4; ntp++) {
                if (ntp < 3)
                    LDSM4T(bn[0], bn[1], bn[2], bn[3], kOff + 32 * (ntp + 1));
                MMA16816F16(acc[2 * ntp],     aF[0], aF[1], aF[2], aF[3], bc[0], bc[1]);
                MMA16816F16(acc[2 * ntp + 1], aF[0], aF[1], aF[2], aF[3], bc[2], bc[3]);
                if (ntp < 3) {
#pragma unroll
                    for (int z = 0; z < 4; z++) bc[z] = bn[z];
                }
            }
            MMA16816F16(accd, aF[0], aF[1], aF[2], aF[3], ONES, ONES);

            if (kt == 3 && !last) {
                *(uint4*)&dst[lk0 * BSTRIDE + lc0 * 8] = na;
                *(uint4*)&dst[lk1 * BSTRIDE + lc1 * 8] = nb;
                const unsigned short* src = gwh + (size_t)(j0 + JT + 64) * FO;
                na = *(const uint4*)(src + (size_t)lk0 * FO + lc0 * 8);
                nb = *(const uint4*)(src + (size_t)lk1 * FO + lc1 * 8);
            }

            if (kt < 7) {
                aF[0] = aN[0]; aF[1] = aN[1]; aF[2] = aN[2]; aF[3] = aN[3];
            }
        }

        if (!last) {
            *(uint4*)&dst[(64 + lk0) * BSTRIDE + lc0 * 8] = na;
            *(uint4*)&dst[(64 + lk1) * BSTRIDE + lc1 * 8] = nb;
            distrib(bvNext);
            scoreblk(j0 + JT, 0, aF);
        }
        __syncthreads();
    }

    const float inv0 = 1.f / accd[0];
    const float inv1 = 1.f / accd[2];

    float* ob0 = out + (size_t)(i0 + rw0) * OUTW + hh * FO + c2;
    float* ob1 = ob0 + (size_t)8 * OUTW;
#pragma unroll
    for (int nt = 0; nt < 8; nt++) {
        float2 v0 = make_float2(elu(acc[nt][0] * inv0), elu(acc[nt][1] * inv0));
        float2 v1 = make_float2(elu(acc[nt][2] * inv1), elu(acc[nt][3] * inv1));
        *(float2*)(ob0 + 8 * nt) = v0;
        *(float2*)(ob1 + 8 * nt) = v1;
    }
}

// ---------------------------------------------------------------------------
extern "C" void kernel_launch(void* const* d_in, const int* in_sizes, int n_in,
                              void* d_out, int out_size)
{
    const float* h    = (const float*)d_in[0];  // [N, FIN]
    const int*   mask = (const int*)  d_in[1];  // [N, N]
    const float* W    = (const float*)d_in[2];  // [H, FIN, FO]
    const float* bW   = (const float*)d_in[3];  // [H, FO]
    const float* a_l  = (const float*)d_in[4];  // [H, FO]
    const float* a_r  = (const float*)d_in[5];  // [H, FO]
    const float* bA   = (const float*)d_in[6];  // [H]
    float* out = (float*)d_out;                 // [N, H*FO]

    cudaFuncSetAttribute(wh_mma_kernel,
                         cudaFuncAttributeMaxDynamicSharedMemorySize, WH_SMEM);
    cudaFuncSetAttribute(gat_attn_mma_kernel,
                         cudaFuncAttributeMaxDynamicSharedMemorySize, ATTN_SMEM);

    prep_kernel<<<1024, 256>>>(h, W, mask);
    wh_mma_kernel<<<dim3(NN / 128, NH), 256, WH_SMEM>>>(bW, a_l, a_r, bA);
    gat_attn_mma_kernel<<<dim3(NN / 128, NH), 256, ATTN_SMEM>>>(out);
}